// round 1
// baseline (speedup 1.0000x reference)
#include <cuda_runtime.h>
#include <cuda_bf16.h>
#include <math.h>
#include <stdint.h>

// Problem constants
#define BATCH 8
#define C 256
#define H 64
#define W 64
#define HW 4096            // H*W
#define NPIX 32768         // BATCH*HW
#define KK 9
#define CK 2304            // C*KK
#define CHW (C*HW)

// ---------------- scratch (device globals; no allocation) ----------------
__device__ float g_proj[(size_t)BATCH * CHW];          // 33.5 MB
__device__ float g_off[(size_t)BATCH * 27 * HW];       // 3.5 MB
__device__ float g_col[(size_t)CK * NPIX];             // 302 MB im2col (mask folded)
__device__ float g_inv1[C], g_add1[C], g_inv2[C], g_add2[C];

// ---------------- prep: fold BN + bias into per-channel scale/add --------
__global__ void prep_kernel(const float* __restrict__ p1_b,
                            const float* __restrict__ bn1_g, const float* __restrict__ bn1_b,
                            const float* __restrict__ bn1_m, const float* __restrict__ bn1_v,
                            const float* __restrict__ dcn_b,
                            const float* __restrict__ bn2_g, const float* __restrict__ bn2_b,
                            const float* __restrict__ bn2_m, const float* __restrict__ bn2_v)
{
    int o = threadIdx.x;
    if (o < C) {
        float inv1 = bn1_g[o] / sqrtf(bn1_v[o] + 1e-5f);
        g_inv1[o] = inv1;
        g_add1[o] = bn1_b[o] - bn1_m[o] * inv1 + p1_b[o] * inv1;
        float inv2 = bn2_g[o] / sqrtf(bn2_v[o] + 1e-5f);
        g_inv2[o] = inv2;
        g_add2[o] = bn2_b[o] - bn2_m[o] * inv2 + dcn_b[o] * inv2;
    }
}

// ---------------- tiled fp32 GEMM (shared by proj and DCN) ---------------
// C[M,N] = A[M,K] * B[K,N]; PROJ: B = feature (per-batch NCHW view), epilogue
// BN1 -> g_proj. !PROJ: B = g_col, epilogue BN2 + proj residual + relu -> out.
#define BM 128
#define BN 128
#define BKT 16
#define TM 8
#define TN 8

template<bool PROJ>
__global__ void __launch_bounds__(256)
gemm_kernel(const float* __restrict__ A, const float* __restrict__ Bsrc,
            float* __restrict__ Cout, int Kdim)
{
    __shared__ float sA[BKT][BM + 4];
    __shared__ float sB[BKT][BN + 4];

    const int tid = threadIdx.x;
    const int pb0 = blockIdx.x * BN;       // pixel tile start (global pixel index)
    const int m0  = blockIdx.y * BM;       // output-channel tile start

    const int bb  = pb0 >> 12;             // batch index (tile never crosses batch: 4096 % 128 == 0)
    const int hw0 = pb0 & 4095;

    const float* Bbase;
    int strideK;
    if (PROJ) { Bbase = Bsrc + (size_t)bb * CHW + hw0; strideK = HW; }
    else      { Bbase = g_col + pb0;                   strideK = NPIX; }

    const int rowl = (tid >> 4) * TM;      // local m offset
    const int coll = (tid & 15) * TN;      // local n offset

    float acc[TM][TN];
#pragma unroll
    for (int i = 0; i < TM; i++)
#pragma unroll
        for (int j = 0; j < TN; j++) acc[i][j] = 0.0f;

    const int nK = Kdim / BKT;
    for (int kt = 0; kt < nK; kt++) {
        const int k0 = kt * BKT;
        // load A tile (BM x BKT), store transposed sA[kk][m]
#pragma unroll
        for (int l = 0; l < 2; l++) {
            int f = tid + l * 256;                 // 0..511 float4 slots
            int row = f >> 2;                      // 0..127
            int jc  = (f & 3) * 4;                 // 0,4,8,12
            float4 v = *(const float4*)(A + (size_t)(m0 + row) * Kdim + k0 + jc);
            sA[jc + 0][row] = v.x;
            sA[jc + 1][row] = v.y;
            sA[jc + 2][row] = v.z;
            sA[jc + 3][row] = v.w;
        }
        // load B tile (BKT x BN)
#pragma unroll
        for (int l = 0; l < 2; l++) {
            int f = tid + l * 256;
            int kk = f >> 5;                       // 0..15
            int jc = (f & 31) * 4;                 // 0..124
            float4 v = *(const float4*)(Bbase + (size_t)(k0 + kk) * strideK + jc);
            *(float4*)&sB[kk][jc] = v;
        }
        __syncthreads();

#pragma unroll
        for (int kk = 0; kk < BKT; kk++) {
            float a[TM], b[TN];
#pragma unroll
            for (int i = 0; i < TM; i++) a[i] = sA[kk][rowl + i];
#pragma unroll
            for (int j = 0; j < TN; j++) b[j] = sB[kk][coll + j];
#pragma unroll
            for (int i = 0; i < TM; i++)
#pragma unroll
                for (int j = 0; j < TN; j++) acc[i][j] += a[i] * b[j];
        }
        __syncthreads();
    }

    // epilogue
    if (PROJ) {
        float* ob = g_proj + (size_t)bb * CHW + hw0;
#pragma unroll
        for (int i = 0; i < TM; i++) {
            int o = m0 + rowl + i;
            float inv = g_inv1[o], add = g_add1[o];
#pragma unroll
            for (int j = 0; j < TN; j++)
                ob[(size_t)o * HW + coll + j] = acc[i][j] * inv + add;
        }
    } else {
        const float* pr = g_proj + (size_t)bb * CHW + hw0;
        float* ob = Cout + (size_t)bb * CHW + hw0;
#pragma unroll
        for (int i = 0; i < TM; i++) {
            int o = m0 + rowl + i;
            float inv = g_inv2[o], add = g_add2[o];
#pragma unroll
            for (int j = 0; j < TN; j++) {
                float v = acc[i][j] * inv + add + pr[(size_t)o * HW + coll + j];
                ob[(size_t)o * HW + coll + j] = fmaxf(v, 0.0f);
            }
        }
    }
}

// ---------------- offset conv3x3 over concat(flipped, proj) --------------
// g_off[b, o(27), h, w] ; input channels 0..255 = flipped feature, 256..511 = proj
__global__ void __launch_bounds__(256)
off_conv_kernel(const float* __restrict__ feature,
                const float* __restrict__ off_w, const float* __restrict__ off_b)
{
    __shared__ float s_in[18][20];
    __shared__ __align__(16) float s_w[244];

    const int tid = threadIdx.x;
    const int tx = tid & 15, ty = tid >> 4;
    const int x0 = blockIdx.x * 16, y0 = blockIdx.y * 16;
    const int bz = blockIdx.z;

    float acc[27];
#pragma unroll
    for (int o = 0; o < 27; o++) acc[o] = 0.0f;

    for (int ci = 0; ci < 512; ci++) {
        // stage 18x18 input tile (with halo)
        for (int i = tid; i < 324; i += 256) {
            int iy = i / 18, ix = i - iy * 18;
            int gy = y0 - 1 + iy, gx = x0 - 1 + ix;
            float v = 0.0f;
            if (gy >= 0 && gy < H && gx >= 0 && gx < W) {
                if (ci < 256)
                    v = feature[((size_t)(bz * 256 + ci) * H + gy) * W + (63 - gx)];
                else
                    v = g_proj[((size_t)(bz * 256 + (ci - 256)) * H + gy) * W + gx];
            }
            s_in[iy][ix] = v;
        }
        // stage 243 weights for this input channel
        if (tid < 243) {
            int o = tid / 9, t = tid - o * 9;
            s_w[tid] = off_w[((size_t)o * 512 + ci) * 9 + t];
        }
        __syncthreads();

        float px[9];
#pragma unroll
        for (int r = 0; r < 3; r++)
#pragma unroll
            for (int s = 0; s < 3; s++) px[r * 3 + s] = s_in[ty + r][tx + s];

        const float4* w4 = (const float4*)s_w;
#pragma unroll
        for (int j = 0; j < 60; j++) {
            float4 wv = w4[j];
            int i0 = j * 4;
            acc[(i0    ) / 9] += px[(i0    ) % 9] * wv.x;
            acc[(i0 + 1) / 9] += px[(i0 + 1) % 9] * wv.y;
            acc[(i0 + 2) / 9] += px[(i0 + 2) % 9] * wv.z;
            acc[(i0 + 3) / 9] += px[(i0 + 3) % 9] * wv.w;
        }
        acc[26] += px[6] * s_w[240];
        acc[26] += px[7] * s_w[241];
        acc[26] += px[8] * s_w[242];
        __syncthreads();
    }

    const int hw = (y0 + ty) * W + (x0 + tx);
#pragma unroll
    for (int o = 0; o < 27; o++)
        g_off[((size_t)(bz * 27 + o)) * HW + hw] = acc[o] + off_b[o];
}

// ---------------- deformable bilinear sampling -> im2col (mask folded) ---
__global__ void __launch_bounds__(256)
sample_kernel(const float* __restrict__ feature)
{
    const int tid = threadIdx.x;
    const int w  = tid & 63;
    const int cg = tid >> 6;          // 4 channel groups of 64
    const int h  = blockIdx.x;
    const int k  = blockIdx.y;
    const int b  = blockIdx.z;

    const int hw = h * W + w;
    const int p  = b * HW + hw;
    const size_t obase = (size_t)(b * 27) * HW + hw;

    const float dy = g_off[obase + (size_t)k * HW];
    const float dx = g_off[obase + (size_t)(9 + k) * HW];
    const float mr = g_off[obase + (size_t)(18 + k) * HW];
    const float m  = 1.0f / (1.0f + expf(-mr));

    const int ky = k / 3 - 1, kx = k % 3 - 1;
    const float py = (float)(h + ky) + dy;
    const float px = (float)(w + kx) + dx;

    const float y0f = floorf(py), x0f = floorf(px);
    const float wy = py - y0f, wx = px - x0f;
    const int y0 = (int)y0f, x0 = (int)x0f;
    const int y1 = y0 + 1,   x1 = x0 + 1;

    const bool vy0 = (y0 >= 0) && (y0 < H);
    const bool vy1 = (y1 >= 0) && (y1 < H);
    const bool vx0 = (x0 >= 0) && (x0 < W);
    const bool vx1 = (x1 >= 0) && (x1 < W);

    float w00 = (1.0f - wy) * (1.0f - wx) * ((vy0 && vx0) ? 1.0f : 0.0f);
    float w01 = (1.0f - wy) * wx          * ((vy0 && vx1) ? 1.0f : 0.0f);
    float w10 = wy * (1.0f - wx)          * ((vy1 && vx0) ? 1.0f : 0.0f);
    float w11 = wy * wx                   * ((vy1 && vx1) ? 1.0f : 0.0f);
    w00 *= m; w01 *= m; w10 *= m; w11 *= m;

    const int yc0 = min(max(y0, 0), H - 1);
    const int yc1 = min(max(y1, 0), H - 1);
    const int xc0 = min(max(x0, 0), W - 1);
    const int xc1 = min(max(x1, 0), W - 1);

    // flipped[b,c,y,x] = feature[b,c,y,63-x]
    const int a00 = yc0 * W + (63 - xc0);
    const int a01 = yc0 * W + (63 - xc1);
    const int a10 = yc1 * W + (63 - xc0);
    const int a11 = yc1 * W + (63 - xc1);

    const float* fb = feature + (size_t)b * CHW + (size_t)(cg * 64) * HW;
    float* cb = g_col + ((size_t)(cg * 64) * KK + k) * NPIX + p;

#pragma unroll 4
    for (int c = 0; c < 64; c++) {
        float v = w00 * fb[a00] + w01 * fb[a01] + w10 * fb[a10] + w11 * fb[a11];
        *cb = v;
        fb += HW;
        cb += (size_t)KK * NPIX;
    }
}

// ---------------- launch -------------------------------------------------
extern "C" void kernel_launch(void* const* d_in, const int* in_sizes, int n_in,
                              void* d_out, int out_size)
{
    const float* feature = (const float*)d_in[0];
    const float* p1_w    = (const float*)d_in[1];
    const float* p1_b    = (const float*)d_in[2];
    const float* bn1_g   = (const float*)d_in[3];
    const float* bn1_b   = (const float*)d_in[4];
    const float* bn1_m   = (const float*)d_in[5];
    const float* bn1_v   = (const float*)d_in[6];
    const float* off_w   = (const float*)d_in[7];
    const float* off_b   = (const float*)d_in[8];
    const float* dcn_w   = (const float*)d_in[9];
    const float* dcn_b   = (const float*)d_in[10];
    const float* bn2_g   = (const float*)d_in[11];
    const float* bn2_b   = (const float*)d_in[12];
    const float* bn2_m   = (const float*)d_in[13];
    const float* bn2_v   = (const float*)d_in[14];

    prep_kernel<<<1, 256>>>(p1_b, bn1_g, bn1_b, bn1_m, bn1_v,
                            dcn_b, bn2_g, bn2_b, bn2_m, bn2_v);

    dim3 gg(NPIX / BN, C / BM);
    gemm_kernel<true><<<gg, 256>>>(p1_w, feature, nullptr, 256);

    off_conv_kernel<<<dim3(4, 4, BATCH), 256>>>(feature, off_w, off_b);

    sample_kernel<<<dim3(H, KK, BATCH), 256>>>(feature);

    gemm_kernel<false><<<gg, 256>>>(dcn_w, nullptr, (float*)d_out, CK);
}

// round 3
// speedup vs baseline: 1.3905x; 1.3905x over previous
#include <cuda_runtime.h>
#include <cuda_bf16.h>
#include <math.h>
#include <stdint.h>

// Problem constants
#define BATCH 8
#define C 256
#define H 64
#define W 64
#define HW 4096
#define NPIX 32768
#define KK 9
#define CK 2304
#define CHW (C*HW)

// ---------------- scratch (device globals; no allocation) ----------------
__device__ float g_proj[(size_t)BATCH * CHW];                    // 33.5 MB
__device__ float g_off[(size_t)BATCH * 27 * HW];                 // 3.5 MB
__device__ __nv_bfloat16 g_colh[(size_t)CK * NPIX];              // 151 MB
__device__ __nv_bfloat16 g_coll[(size_t)CK * NPIX];              // 151 MB
__device__ __nv_bfloat16 g_wh[(size_t)C * CK];                   // 1.2 MB (scaled by inv2)
__device__ __nv_bfloat16 g_wl[(size_t)C * CK];
__device__ float g_inv1[C], g_add1[C], g_inv2[C], g_add2[C];

// ================= mma.sync / ldmatrix / cp.async helpers =================
__device__ __forceinline__ uint32_t smem_to_u32(const void* p) {
    uint32_t a;
    asm("{ .reg .u64 t; cvta.to.shared.u64 t, %1; cvt.u32.u64 %0, t; }" : "=r"(a) : "l"(p));
    return a;
}
__device__ __forceinline__ void cp16(uint32_t s, const void* g) {
    asm volatile("cp.async.cg.shared.global [%0], [%1], 16;" :: "r"(s), "l"(g));
}
#define CP_COMMIT() asm volatile("cp.async.commit_group;" ::: "memory")
#define CP_WAIT(n)  asm volatile("cp.async.wait_group %0;" :: "n"(n) : "memory")

__device__ __forceinline__ void ldsm4(uint32_t* r, uint32_t addr) {
    asm volatile("ldmatrix.sync.aligned.m8n8.x4.shared.b16 {%0,%1,%2,%3}, [%4];"
        : "=r"(r[0]), "=r"(r[1]), "=r"(r[2]), "=r"(r[3]) : "r"(addr));
}
__device__ __forceinline__ void ldsm4t(uint32_t* r, uint32_t addr) {
    asm volatile("ldmatrix.sync.aligned.m8n8.x4.trans.shared.b16 {%0,%1,%2,%3}, [%4];"
        : "=r"(r[0]), "=r"(r[1]), "=r"(r[2]), "=r"(r[3]) : "r"(addr));
}
__device__ __forceinline__ void mma16816(float* c, const uint32_t* a, const uint32_t* b) {
    asm volatile("mma.sync.aligned.m16n8k16.row.col.f32.bf16.bf16.f32 "
        "{%0,%1,%2,%3}, {%4,%5,%6,%7}, {%8,%9}, {%0,%1,%2,%3};"
        : "+f"(c[0]), "+f"(c[1]), "+f"(c[2]), "+f"(c[3])
        : "r"(a[0]), "r"(a[1]), "r"(a[2]), "r"(a[3]), "r"(b[0]), "r"(b[1]));
}

// ---------------- prep -----------------------------------------------------
__global__ void prep_kernel(const float* __restrict__ p1_b,
                            const float* __restrict__ bn1_g, const float* __restrict__ bn1_b,
                            const float* __restrict__ bn1_m, const float* __restrict__ bn1_v,
                            const float* __restrict__ dcn_b,
                            const float* __restrict__ bn2_g, const float* __restrict__ bn2_b,
                            const float* __restrict__ bn2_m, const float* __restrict__ bn2_v)
{
    int o = threadIdx.x;
    if (o < C) {
        float inv1 = bn1_g[o] / sqrtf(bn1_v[o] + 1e-5f);
        g_inv1[o] = inv1;
        g_add1[o] = bn1_b[o] - bn1_m[o] * inv1 + p1_b[o] * inv1;
        float inv2 = bn2_g[o] / sqrtf(bn2_v[o] + 1e-5f);
        g_inv2[o] = inv2;
        g_add2[o] = bn2_b[o] - bn2_m[o] * inv2 + dcn_b[o] * inv2;
    }
}

// split dcn weights (scaled by inv2) into bf16 hi/lo
__global__ void split_w_kernel(const float* __restrict__ dcn_w)
{
    int idx = blockIdx.x * 256 + threadIdx.x;
    if (idx < C * CK) {
        int o = idx / CK;
        float v = dcn_w[idx] * g_inv2[o];
        __nv_bfloat16 hi = __float2bfloat16(v);
        float lo = v - __bfloat162float(hi);
        g_wh[idx] = hi;
        g_wl[idx] = __float2bfloat16(lo);
    }
}

// ---------------- proj GEMM (fp32) -----------------------------------------
#define BM 128
#define BN 128
#define BKT 16
#define TM 8
#define TN 8

__global__ void __launch_bounds__(256)
proj_gemm_kernel(const float* __restrict__ A, const float* __restrict__ Bsrc)
{
    __shared__ float sA[BKT][BM + 4];
    __shared__ float sB[BKT][BN + 4];

    const int tid = threadIdx.x;
    const int pb0 = blockIdx.x * BN;
    const int m0  = blockIdx.y * BM;
    const int bb  = pb0 >> 12;
    const int hw0 = pb0 & 4095;

    const float* Bbase = Bsrc + (size_t)bb * CHW + hw0;
    const int strideK = HW;

    const int rowl = (tid >> 4) * TM;
    const int coll = (tid & 15) * TN;

    float acc[TM][TN];
#pragma unroll
    for (int i = 0; i < TM; i++)
#pragma unroll
        for (int j = 0; j < TN; j++) acc[i][j] = 0.0f;

    const int Kdim = 256;
    for (int kt = 0; kt < Kdim / BKT; kt++) {
        const int k0 = kt * BKT;
#pragma unroll
        for (int l = 0; l < 2; l++) {
            int f = tid + l * 256;
            int row = f >> 2;
            int jc  = (f & 3) * 4;
            float4 v = *(const float4*)(A + (size_t)(m0 + row) * Kdim + k0 + jc);
            sA[jc + 0][row] = v.x; sA[jc + 1][row] = v.y;
            sA[jc + 2][row] = v.z; sA[jc + 3][row] = v.w;
        }
#pragma unroll
        for (int l = 0; l < 2; l++) {
            int f = tid + l * 256;
            int kk = f >> 5;
            int jc = (f & 31) * 4;
            float4 v = *(const float4*)(Bbase + (size_t)(k0 + kk) * strideK + jc);
            *(float4*)&sB[kk][jc] = v;
        }
        __syncthreads();
#pragma unroll
        for (int kk = 0; kk < BKT; kk++) {
            float a[TM], b[TN];
#pragma unroll
            for (int i = 0; i < TM; i++) a[i] = sA[kk][rowl + i];
#pragma unroll
            for (int j = 0; j < TN; j++) b[j] = sB[kk][coll + j];
#pragma unroll
            for (int i = 0; i < TM; i++)
#pragma unroll
                for (int j = 0; j < TN; j++) acc[i][j] += a[i] * b[j];
        }
        __syncthreads();
    }

    float* ob = g_proj + (size_t)bb * CHW + hw0;
#pragma unroll
    for (int i = 0; i < TM; i++) {
        int o = m0 + rowl + i;
        float inv = g_inv1[o], add = g_add1[o];
#pragma unroll
        for (int j = 0; j < TN; j++)
            ob[(size_t)o * HW + coll + j] = acc[i][j] * inv + add;
    }
}

// ---------------- offset conv3x3 -------------------------------------------
__global__ void __launch_bounds__(256)
off_conv_kernel(const float* __restrict__ feature,
                const float* __restrict__ off_w, const float* __restrict__ off_b)
{
    __shared__ float s_in[18][20];
    __shared__ __align__(16) float s_w[244];

    const int tid = threadIdx.x;
    const int tx = tid & 15, ty = tid >> 4;
    const int x0 = blockIdx.x * 16, y0 = blockIdx.y * 16;
    const int bz = blockIdx.z;

    float acc[27];
#pragma unroll
    for (int o = 0; o < 27; o++) acc[o] = 0.0f;

    for (int ci = 0; ci < 512; ci++) {
        for (int i = tid; i < 324; i += 256) {
            int iy = i / 18, ix = i - iy * 18;
            int gy = y0 - 1 + iy, gx = x0 - 1 + ix;
            float v = 0.0f;
            if (gy >= 0 && gy < H && gx >= 0 && gx < W) {
                if (ci < 256)
                    v = feature[((size_t)(bz * 256 + ci) * H + gy) * W + (63 - gx)];
                else
                    v = g_proj[((size_t)(bz * 256 + (ci - 256)) * H + gy) * W + gx];
            }
            s_in[iy][ix] = v;
        }
        if (tid < 243) {
            int o = tid / 9, t = tid - o * 9;
            s_w[tid] = off_w[((size_t)o * 512 + ci) * 9 + t];
        }
        __syncthreads();

        float px[9];
#pragma unroll
        for (int r = 0; r < 3; r++)
#pragma unroll
            for (int s = 0; s < 3; s++) px[r * 3 + s] = s_in[ty + r][tx + s];

        const float4* w4 = (const float4*)s_w;
#pragma unroll
        for (int j = 0; j < 60; j++) {
            float4 wv = w4[j];
            int i0 = j * 4;
            acc[(i0    ) / 9] += px[(i0    ) % 9] * wv.x;
            acc[(i0 + 1) / 9] += px[(i0 + 1) % 9] * wv.y;
            acc[(i0 + 2) / 9] += px[(i0 + 2) % 9] * wv.z;
            acc[(i0 + 3) / 9] += px[(i0 + 3) % 9] * wv.w;
        }
        acc[26] += px[6] * s_w[240];
        acc[26] += px[7] * s_w[241];
        acc[26] += px[8] * s_w[242];
        __syncthreads();
    }

    const int hw = (y0 + ty) * W + (x0 + tx);
#pragma unroll
    for (int o = 0; o < 27; o++)
        g_off[((size_t)(bz * 27 + o)) * HW + hw] = acc[o] + off_b[o];
}

// ---------------- deformable sampling -> bf16 hi/lo im2col -----------------
__global__ void __launch_bounds__(256)
sample_kernel(const float* __restrict__ feature)
{
    const int tid = threadIdx.x;
    const int w  = tid & 63;
    const int cg = tid >> 6;
    const int h  = blockIdx.x;
    const int k  = blockIdx.y;
    const int b  = blockIdx.z;

    const int hw = h * W + w;
    const int p  = b * HW + hw;
    const size_t obase = (size_t)(b * 27) * HW + hw;

    const float dy = g_off[obase + (size_t)k * HW];
    const float dx = g_off[obase + (size_t)(9 + k) * HW];
    const float mr = g_off[obase + (size_t)(18 + k) * HW];
    const float m  = 1.0f / (1.0f + expf(-mr));

    const int ky = k / 3 - 1, kx = k % 3 - 1;
    const float py = (float)(h + ky) + dy;
    const float px = (float)(w + kx) + dx;

    const float y0f = floorf(py), x0f = floorf(px);
    const float wy = py - y0f, wx = px - x0f;
    const int y0 = (int)y0f, x0 = (int)x0f;
    const int y1 = y0 + 1,   x1 = x0 + 1;

    const bool vy0 = (y0 >= 0) && (y0 < H);
    const bool vy1 = (y1 >= 0) && (y1 < H);
    const bool vx0 = (x0 >= 0) && (x0 < W);
    const bool vx1 = (x1 >= 0) && (x1 < W);

    float w00 = (1.0f - wy) * (1.0f - wx) * ((vy0 && vx0) ? 1.0f : 0.0f);
    float w01 = (1.0f - wy) * wx          * ((vy0 && vx1) ? 1.0f : 0.0f);
    float w10 = wy * (1.0f - wx)          * ((vy1 && vx0) ? 1.0f : 0.0f);
    float w11 = wy * wx                   * ((vy1 && vx1) ? 1.0f : 0.0f);
    w00 *= m; w01 *= m; w10 *= m; w11 *= m;

    const int yc0 = min(max(y0, 0), H - 1);
    const int yc1 = min(max(y1, 0), H - 1);
    const int xc0 = min(max(x0, 0), W - 1);
    const int xc1 = min(max(x1, 0), W - 1);

    const int a00 = yc0 * W + (63 - xc0);
    const int a01 = yc0 * W + (63 - xc1);
    const int a10 = yc1 * W + (63 - xc0);
    const int a11 = yc1 * W + (63 - xc1);

    const float* fb = feature + (size_t)b * CHW + (size_t)(cg * 64) * HW;
    size_t cidx = ((size_t)(cg * 64) * KK + k) * NPIX + p;

#pragma unroll 4
    for (int c = 0; c < 64; c++) {
        float v = w00 * fb[a00] + w01 * fb[a01] + w10 * fb[a10] + w11 * fb[a11];
        __nv_bfloat16 hi = __float2bfloat16(v);
        g_colh[cidx] = hi;
        g_coll[cidx] = __float2bfloat16(v - __bfloat162float(hi));
        fb += HW;
        cidx += (size_t)KK * NPIX;
    }
}

// ---------------- DCN GEMM: mma.sync bf16 split-precision ------------------
// CTA 128x128, 8 warps (warp tile 64x32), K = 2304 in 72 chunks of 32.
// SMEM stage: Ah | Al (128x40 halves each) | Bh | Bl (32x136 halves each)
#define DCN_NCH 72
#define A_STRIDE 40
#define B_STRIDE 136
#define A_BYTES (128 * A_STRIDE * 2)                 // 10240
#define B_BYTES (32 * B_STRIDE * 2)                  // 8704
#define STAGE_BYTES (2 * A_BYTES + 2 * B_BYTES)      // 37888
#define DCN_SMEM (2 * STAGE_BYTES)                   // 75776

__global__ void __launch_bounds__(256, 1)
dcn_gemm_kernel(float* __restrict__ out)
{
    extern __shared__ char smem[];
    const uint32_t sbase = smem_to_u32(smem);
    const int tid = threadIdx.x;
    const int lane = tid & 31;
    const int wid = tid >> 5;

    const int n0 = blockIdx.x * 128;
    const int m0 = blockIdx.y * 128;
    const int bb = n0 >> 12;
    const int hw0 = n0 & 4095;
    const int wm = (wid >> 2) * 64;    // warp m offset (0 / 64)
    const int wn = (wid & 3) * 32;     // warp n offset (0/32/64/96)

    const __nv_bfloat16* wh = g_wh + (size_t)m0 * CK;
    const __nv_bfloat16* wl = g_wl + (size_t)m0 * CK;

    float acc[4][4][4];
#pragma unroll
    for (int i = 0; i < 4; i++)
#pragma unroll
        for (int j = 0; j < 4; j++)
#pragma unroll
            for (int t = 0; t < 4; t++) acc[i][j][t] = 0.0f;

    auto load_chunk = [&](int st, int kt) {
        const uint32_t s = sbase + st * STAGE_BYTES;
        const int k0 = kt * 32;
#pragma unroll
        for (int i = 0; i < 2; i++) {
            int idx = i * 256 + tid;            // 0..511
            int r = idx >> 2, kseg = idx & 3;
            size_t go = (size_t)r * CK + k0 + kseg * 8;
            uint32_t so = (uint32_t)(r * A_STRIDE + kseg * 8) * 2;
            cp16(s + so, wh + go);
            cp16(s + A_BYTES + so, wl + go);
        }
#pragma unroll
        for (int i = 0; i < 2; i++) {
            int idx = i * 256 + tid;
            int kr = idx >> 4, nseg = idx & 15;
            size_t go = (size_t)(k0 + kr) * NPIX + n0 + nseg * 8;
            uint32_t so = (uint32_t)(kr * B_STRIDE + nseg * 8) * 2;
            cp16(s + 2 * A_BYTES + so, g_colh + go);
            cp16(s + 2 * A_BYTES + B_BYTES + so, g_coll + go);
        }
        CP_COMMIT();
    };

    load_chunk(0, 0);

    for (int kt = 0; kt < DCN_NCH; kt++) {
        const int st = kt & 1;
        if (kt + 1 < DCN_NCH) { load_chunk(st ^ 1, kt + 1); CP_WAIT(1); }
        else                  { CP_WAIT(0); }
        __syncthreads();

        const uint32_t sAh = sbase + st * STAGE_BYTES;
        const uint32_t sAl = sAh + A_BYTES;
        const uint32_t sBh = sAh + 2 * A_BYTES;
        const uint32_t sBl = sBh + B_BYTES;

#pragma unroll
        for (int ks = 0; ks < 2; ks++) {
            uint32_t ah[4][4], al[4][4], bh[4][2], bl[4][2];

            const int arow = wm + (lane & 15);
            const int acol = ks * 16 + ((lane >> 4) << 3);
#pragma unroll
            for (int tm = 0; tm < 4; tm++) {
                uint32_t ao = (uint32_t)((arow + tm * 16) * A_STRIDE + acol) * 2;
                ldsm4(ah[tm], sAh + ao);
                ldsm4(al[tm], sAl + ao);
            }
            const int bkrow = ks * 16 + (lane & 15);
#pragma unroll
            for (int ng = 0; ng < 2; ng++) {
                const int bcol = wn + ng * 16 + ((lane >> 4) << 3);
                uint32_t bo = (uint32_t)(bkrow * B_STRIDE + bcol) * 2;
                uint32_t t[4];
                ldsm4t(t, sBh + bo);
                bh[2*ng][0] = t[0]; bh[2*ng][1] = t[1];
                bh[2*ng+1][0] = t[2]; bh[2*ng+1][1] = t[3];
                ldsm4t(t, sBl + bo);
                bl[2*ng][0] = t[0]; bl[2*ng][1] = t[1];
                bl[2*ng+1][0] = t[2]; bl[2*ng+1][1] = t[3];
            }
#pragma unroll
            for (int tm = 0; tm < 4; tm++)
#pragma unroll
                for (int tn = 0; tn < 4; tn++) {
                    mma16816(acc[tm][tn], ah[tm], bh[tn]);
                    mma16816(acc[tm][tn], ah[tm], bl[tn]);
                    mma16816(acc[tm][tn], al[tm], bh[tn]);
                }
        }
        __syncthreads();
    }

    // epilogue: c frag layout (row = lane>>2 [+8], col = (lane&3)*2 [+1])
    const int rowl = lane >> 2;
    const int colp = (lane & 3) * 2;
#pragma unroll
    for (int tm = 0; tm < 4; tm++) {
#pragma unroll
        for (int half = 0; half < 2; half++) {
            const int m = m0 + wm + tm * 16 + rowl + half * 8;
            const float add = g_add2[m];
            const float* pr = g_proj + ((size_t)bb * C + m) * HW + hw0 + wn + colp;
            float*       ob = out    + ((size_t)bb * C + m) * HW + hw0 + wn + colp;
#pragma unroll
            for (int tn = 0; tn < 4; tn++) {
                float2 p = *(const float2*)(pr + tn * 8);
                float2 r;
                r.x = fmaxf(acc[tm][tn][half * 2 + 0] + add + p.x, 0.0f);
                r.y = fmaxf(acc[tm][tn][half * 2 + 1] + add + p.y, 0.0f);
                *(float2*)(ob + tn * 8) = r;
            }
        }
    }
}

// ---------------- launch ----------------------------------------------------
extern "C" void kernel_launch(void* const* d_in, const int* in_sizes, int n_in,
                              void* d_out, int out_size)
{
    const float* feature = (const float*)d_in[0];
    const float* p1_w    = (const float*)d_in[1];
    const float* p1_b    = (const float*)d_in[2];
    const float* bn1_g   = (const float*)d_in[3];
    const float* bn1_b   = (const float*)d_in[4];
    const float* bn1_m   = (const float*)d_in[5];
    const float* bn1_v   = (const float*)d_in[6];
    const float* off_w   = (const float*)d_in[7];
    const float* off_b   = (const float*)d_in[8];
    const float* dcn_w   = (const float*)d_in[9];
    const float* dcn_b   = (const float*)d_in[10];
    const float* bn2_g   = (const float*)d_in[11];
    const float* bn2_b   = (const float*)d_in[12];
    const float* bn2_m   = (const float*)d_in[13];
    const float* bn2_v   = (const float*)d_in[14];

    cudaFuncSetAttribute(dcn_gemm_kernel,
                         cudaFuncAttributeMaxDynamicSharedMemorySize, DCN_SMEM);

    prep_kernel<<<1, 256>>>(p1_b, bn1_g, bn1_b, bn1_m, bn1_v,
                            dcn_b, bn2_g, bn2_b, bn2_m, bn2_v);
    split_w_kernel<<<(C * CK + 255) / 256, 256>>>(dcn_w);

    proj_gemm_kernel<<<dim3(NPIX / BN, C / BM), 256>>>(p1_w, feature);

    off_conv_kernel<<<dim3(4, 4, BATCH), 256>>>(feature, off_w, off_b);

    sample_kernel<<<dim3(H, KK, BATCH), 256>>>(feature);

    dcn_gemm_kernel<<<dim3(NPIX / 128, C / 128), 256, DCN_SMEM>>>((float*)d_out);
}

// round 4
// speedup vs baseline: 2.4674x; 1.7744x over previous
#include <cuda_runtime.h>
#include <cuda_bf16.h>
#include <math.h>
#include <stdint.h>

// Problem constants
#define BATCH 8
#define C 256
#define H 64
#define W 64
#define HW 4096
#define NPIX 32768
#define KK 9
#define CK 2304
#define CHW (C*HW)
#define PDIM 66
#define PP (PDIM*PDIM)     // 4356 padded positions per batch

// ---------------- scratch (device globals; no allocation) ----------------
__device__ float g_proj[(size_t)BATCH * CHW];                    // 33.5 MB
__device__ float g_off[(size_t)BATCH * 27 * HW];                 // 3.5 MB
__device__ __nv_bfloat16 g_colh[(size_t)CK * NPIX];              // 151 MB
__device__ __nv_bfloat16 g_coll[(size_t)CK * NPIX];              // 151 MB
__device__ __nv_bfloat16 g_wh[(size_t)C * CK];                   // dcn weights hi (scaled)
__device__ __nv_bfloat16 g_wl[(size_t)C * CK];
__device__ __nv_bfloat16 g_xh[(size_t)BATCH * PP * 512];         // 35.7 MB X^T padded hi
__device__ __nv_bfloat16 g_xl[(size_t)BATCH * PP * 512];         // lo
__device__ __nv_bfloat16 g_owh[(size_t)9 * 32 * 512];            // offset weights hi
__device__ __nv_bfloat16 g_owl[(size_t)9 * 32 * 512];
__device__ float g_inv1[C], g_add1[C], g_inv2[C], g_add2[C];

// ================= mma.sync / ldmatrix / cp.async helpers =================
__device__ __forceinline__ uint32_t smem_to_u32(const void* p) {
    uint32_t a;
    asm("{ .reg .u64 t; cvta.to.shared.u64 t, %1; cvt.u32.u64 %0, t; }" : "=r"(a) : "l"(p));
    return a;
}
__device__ __forceinline__ void cp16(uint32_t s, const void* g) {
    asm volatile("cp.async.cg.shared.global [%0], [%1], 16;" :: "r"(s), "l"(g));
}
#define CP_COMMIT() asm volatile("cp.async.commit_group;" ::: "memory")
#define CP_WAIT(n)  asm volatile("cp.async.wait_group %0;" :: "n"(n) : "memory")

__device__ __forceinline__ void ldsm4(uint32_t* r, uint32_t addr) {
    asm volatile("ldmatrix.sync.aligned.m8n8.x4.shared.b16 {%0,%1,%2,%3}, [%4];"
        : "=r"(r[0]), "=r"(r[1]), "=r"(r[2]), "=r"(r[3]) : "r"(addr));
}
__device__ __forceinline__ void ldsm4t(uint32_t* r, uint32_t addr) {
    asm volatile("ldmatrix.sync.aligned.m8n8.x4.trans.shared.b16 {%0,%1,%2,%3}, [%4];"
        : "=r"(r[0]), "=r"(r[1]), "=r"(r[2]), "=r"(r[3]) : "r"(addr));
}
__device__ __forceinline__ uint32_t lds32(uint32_t addr) {
    uint32_t v;
    asm volatile("ld.shared.b32 %0, [%1];" : "=r"(v) : "r"(addr));
    return v;
}
__device__ __forceinline__ void mma16816(float* c, const uint32_t* a, const uint32_t* b) {
    asm volatile("mma.sync.aligned.m16n8k16.row.col.f32.bf16.bf16.f32 "
        "{%0,%1,%2,%3}, {%4,%5,%6,%7}, {%8,%9}, {%0,%1,%2,%3};"
        : "+f"(c[0]), "+f"(c[1]), "+f"(c[2]), "+f"(c[3])
        : "r"(a[0]), "r"(a[1]), "r"(a[2]), "r"(a[3]), "r"(b[0]), "r"(b[1]));
}

// ---------------- prep -----------------------------------------------------
__global__ void prep_kernel(const float* __restrict__ p1_b,
                            const float* __restrict__ bn1_g, const float* __restrict__ bn1_b,
                            const float* __restrict__ bn1_m, const float* __restrict__ bn1_v,
                            const float* __restrict__ dcn_b,
                            const float* __restrict__ bn2_g, const float* __restrict__ bn2_b,
                            const float* __restrict__ bn2_m, const float* __restrict__ bn2_v)
{
    int o = threadIdx.x;
    if (o < C) {
        float inv1 = bn1_g[o] / sqrtf(bn1_v[o] + 1e-5f);
        g_inv1[o] = inv1;
        g_add1[o] = bn1_b[o] - bn1_m[o] * inv1 + p1_b[o] * inv1;
        float inv2 = bn2_g[o] / sqrtf(bn2_v[o] + 1e-5f);
        g_inv2[o] = inv2;
        g_add2[o] = bn2_b[o] - bn2_m[o] * inv2 + dcn_b[o] * inv2;
    }
}

// split dcn weights (scaled by inv2) into bf16 hi/lo
__global__ void split_w_kernel(const float* __restrict__ dcn_w)
{
    int idx = blockIdx.x * 256 + threadIdx.x;
    if (idx < C * CK) {
        int o = idx / CK;
        float v = dcn_w[idx] * g_inv2[o];
        __nv_bfloat16 hi = __float2bfloat16(v);
        float lo = v - __bfloat162float(hi);
        g_wh[idx] = hi;
        g_wl[idx] = __float2bfloat16(lo);
    }
}

// repack offset weights: off_w[27][512][3][3] -> g_owh/l [tap(9)][32][512]
__global__ void prep_offw_kernel(const float* __restrict__ off_w)
{
    int idx = blockIdx.x * 256 + threadIdx.x;
    if (idx < 9 * 32 * 512) {
        int t = idx >> 14;            // tap
        int r = (idx >> 9) & 31;      // output row (27 used)
        int c = idx & 511;            // input channel
        float v = 0.0f;
        if (r < 27) {
            int kh = t / 3, kw = t % 3;
            v = off_w[((size_t)(r * 512 + c) * 3 + kh) * 3 + kw];
        }
        __nv_bfloat16 hi = __float2bfloat16(v);
        g_owh[idx] = hi;
        g_owl[idx] = __float2bfloat16(v - __bfloat162float(hi));
    }
}

// zero the padding ring of g_xh/g_xl
__global__ void zero_pad_kernel()
{
    int idx = blockIdx.x * 256 + threadIdx.x;
    // 8 batches x 260 pad positions x 512 channels
    if (idx < BATCH * 260 * 512) {
        int c = idx & 511;
        int rest = idx >> 9;
        int pos = rest % 260;
        int b = rest / 260;
        int yp, xp;
        if (pos < 66)       { yp = 0;  xp = pos; }
        else if (pos < 132) { yp = 65; xp = pos - 66; }
        else {
            int i = pos - 132;
            yp = 1 + (i >> 1);
            xp = (i & 1) * 65;
        }
        size_t a = ((size_t)b * PP + yp * PDIM + xp) * 512 + c;
        g_xh[a] = __float2bfloat16(0.0f);
        g_xl[a] = __float2bfloat16(0.0f);
    }
}

// pack concat(flip(feature), proj) transposed -> X^T[b][pad pos][512] hi/lo
// block (32,8): 32x32 tile transpose for fixed (b, y)
__global__ void __launch_bounds__(256)
pack_kernel(const float* __restrict__ feature)
{
    __shared__ float tile[32][33];
    const int tx = threadIdx.x, ty = threadIdx.y;
    const int b = blockIdx.z >> 6;
    const int y = blockIdx.z & 63;
    const int x0 = blockIdx.x * 32;
    const int c0 = blockIdx.y * 32;

#pragma unroll
    for (int j = 0; j < 4; j++) {
        int c = c0 + ty + j * 8;
        int x = x0 + tx;
        float v;
        if (c < 256) v = feature[((size_t)(b * 256 + c) * 64 + y) * 64 + (63 - x)];
        else         v = g_proj[((size_t)(b * 256 + (c - 256)) * 64 + y) * 64 + x];
        tile[ty + j * 8][tx] = v;
    }
    __syncthreads();
#pragma unroll
    for (int j = 0; j < 4; j++) {
        int xl = ty + j * 8;
        float v = tile[tx][xl];
        size_t a = ((size_t)b * PP + (y + 1) * PDIM + (x0 + xl + 1)) * 512 + c0 + tx;
        __nv_bfloat16 hi = __float2bfloat16(v);
        g_xh[a] = hi;
        g_xl[a] = __float2bfloat16(v - __bfloat162float(hi));
    }
}

// ---------------- proj GEMM (fp32) -----------------------------------------
#define BM 128
#define BN 128
#define BKT 16
#define TM 8
#define TN 8

__global__ void __launch_bounds__(256)
proj_gemm_kernel(const float* __restrict__ A, const float* __restrict__ Bsrc)
{
    __shared__ float sA[BKT][BM + 4];
    __shared__ float sB[BKT][BN + 4];

    const int tid = threadIdx.x;
    const int pb0 = blockIdx.x * BN;
    const int m0  = blockIdx.y * BM;
    const int bb  = pb0 >> 12;
    const int hw0 = pb0 & 4095;

    const float* Bbase = Bsrc + (size_t)bb * CHW + hw0;
    const int strideK = HW;

    const int rowl = (tid >> 4) * TM;
    const int coll = (tid & 15) * TN;

    float acc[TM][TN];
#pragma unroll
    for (int i = 0; i < TM; i++)
#pragma unroll
        for (int j = 0; j < TN; j++) acc[i][j] = 0.0f;

    const int Kdim = 256;
    for (int kt = 0; kt < Kdim / BKT; kt++) {
        const int k0 = kt * BKT;
#pragma unroll
        for (int l = 0; l < 2; l++) {
            int f = tid + l * 256;
            int row = f >> 2;
            int jc  = (f & 3) * 4;
            float4 v = *(const float4*)(A + (size_t)(m0 + row) * Kdim + k0 + jc);
            sA[jc + 0][row] = v.x; sA[jc + 1][row] = v.y;
            sA[jc + 2][row] = v.z; sA[jc + 3][row] = v.w;
        }
#pragma unroll
        for (int l = 0; l < 2; l++) {
            int f = tid + l * 256;
            int kk = f >> 5;
            int jc = (f & 31) * 4;
            float4 v = *(const float4*)(Bbase + (size_t)(k0 + kk) * strideK + jc);
            *(float4*)&sB[kk][jc] = v;
        }
        __syncthreads();
#pragma unroll
        for (int kk = 0; kk < BKT; kk++) {
            float a[TM], b[TN];
#pragma unroll
            for (int i = 0; i < TM; i++) a[i] = sA[kk][rowl + i];
#pragma unroll
            for (int j = 0; j < TN; j++) b[j] = sB[kk][coll + j];
#pragma unroll
            for (int i = 0; i < TM; i++)
#pragma unroll
                for (int j = 0; j < TN; j++) acc[i][j] += a[i] * b[j];
        }
        __syncthreads();
    }

    float* ob = g_proj + (size_t)bb * CHW + hw0;
#pragma unroll
    for (int i = 0; i < TM; i++) {
        int o = m0 + rowl + i;
        float inv = g_inv1[o], add = g_add1[o];
#pragma unroll
        for (int j = 0; j < TN; j++)
            ob[(size_t)o * HW + coll + j] = acc[i][j] * inv + add;
    }
}

// ---------------- offset conv as tensor-core GEMM --------------------------
// M=32 (27 used), N=128 pixels (2 image rows), K = 9 taps x 512 channels.
// B slab: 264 padded-position rows x 32 channels, shared across all 9 taps.
#define OC_ROWS 264
#define OC_BSTR 40                                 // smem B elems per row
#define OC_ASTR 40
#define OC_B_BYTES (OC_ROWS * OC_BSTR * 2)         // 21120
#define OC_A_BYTES (9 * 32 * OC_ASTR * 2)          // 23040
#define OC_STAGE (2 * OC_B_BYTES + 2 * OC_A_BYTES) // 88320
#define OC_SMEM (2 * OC_STAGE)                     // 176640

__global__ void __launch_bounds__(256, 1)
off_gemm_kernel(const float* __restrict__ off_b)
{
    extern __shared__ char smem[];
    const uint32_t sbase = smem_to_u32(smem);
    const int tid = threadIdx.x;
    const int lane = tid & 31;
    const int wid = tid >> 5;

    const int n0 = blockIdx.x * 128;
    const int bb = n0 >> 12;
    const int hw0 = n0 & 4095;
    const int h0 = hw0 >> 6;

    const int wm = (wid >> 2) * 16;   // warp m offset (0/16)
    const int wn = (wid & 3) * 32;    // warp n offset (0/32/64/96)

    const size_t pbase = (size_t)bb * PP + h0 * PDIM;

    // per-thread padded-row bases for the 4 n8 tiles
    int rowb[4];
#pragma unroll
    for (int nt = 0; nt < 4; nt++) {
        int nl = wn + nt * 8 + (lane >> 2);
        rowb[nt] = ((nl >> 6) + 1) * PDIM + (nl & 63) + 1;
    }
    const int am = wm + (lane & 15);
    const int acol2 = (lane >> 4) << 3;

    float acc[4][4];
#pragma unroll
    for (int i = 0; i < 4; i++)
#pragma unroll
        for (int j = 0; j < 4; j++) acc[i][j] = 0.0f;

    auto load_chunk = [&](int st, int kc) {
        const uint32_t s = sbase + st * OC_STAGE;
        const int k0 = kc * 32;
        // B: 264 rows x 32ch (4 x 16B per row per buffer)
#pragma unroll
        for (int i = 0; i < 5; i++) {
            int idx = i * 256 + tid;
            if (idx < 1056) {
                int r = idx >> 2, c4 = idx & 3;
                size_t go = (pbase + r) * 512 + k0 + c4 * 8;
                uint32_t so = (uint32_t)(r * OC_BSTR + c4 * 8) * 2;
                cp16(s + so, g_xh + go);
                cp16(s + OC_B_BYTES + so, g_xl + go);
            }
        }
        // A: 288 rows (tap*32+m) x 32ch
#pragma unroll
        for (int i = 0; i < 5; i++) {
            int idx = i * 256 + tid;
            if (idx < 1152) {
                int r = idx >> 2, c4 = idx & 3;
                size_t go = (size_t)r * 512 + k0 + c4 * 8;
                uint32_t so = (uint32_t)(r * OC_ASTR + c4 * 8) * 2;
                cp16(s + 2 * OC_B_BYTES + so, g_owh + go);
                cp16(s + 2 * OC_B_BYTES + OC_A_BYTES + so, g_owl + go);
            }
        }
        CP_COMMIT();
    };

    const int stap[9] = {-PDIM-1, -PDIM, -PDIM+1, -1, 0, 1, PDIM-1, PDIM, PDIM+1};

    load_chunk(0, 0);

    for (int kc = 0; kc < 16; kc++) {
        const int st = kc & 1;
        if (kc + 1 < 16) { load_chunk(st ^ 1, kc + 1); CP_WAIT(1); }
        else             { CP_WAIT(0); }
        __syncthreads();

        const uint32_t sBh = sbase + st * OC_STAGE;
        const uint32_t sBl = sBh + OC_B_BYTES;
        const uint32_t sAh = sBh + 2 * OC_B_BYTES;
        const uint32_t sAl = sAh + OC_A_BYTES;

#pragma unroll
        for (int tap = 0; tap < 9; tap++) {
            const int s_t = stap[tap];
#pragma unroll
            for (int ks = 0; ks < 2; ks++) {
                uint32_t ah[4], al[4];
                uint32_t ao = (uint32_t)((tap * 32 + am) * OC_ASTR + ks * 16 + acol2) * 2;
                ldsm4(ah, sAh + ao);
                ldsm4(al, sAl + ao);
#pragma unroll
                for (int nt = 0; nt < 4; nt++) {
                    int row = rowb[nt] + s_t;
                    uint32_t base = (uint32_t)(row * OC_BSTR + ks * 16 + (lane & 3) * 2) * 2;
                    uint32_t bh[2], bl[2];
                    bh[0] = lds32(sBh + base);
                    bh[1] = lds32(sBh + base + 16);
                    bl[0] = lds32(sBl + base);
                    bl[1] = lds32(sBl + base + 16);
                    mma16816(acc[nt], ah, bh);
                    mma16816(acc[nt], ah, bl);
                    mma16816(acc[nt], al, bh);
                }
            }
        }
        __syncthreads();
    }

    // epilogue: write rows <27 of g_off[b][27][HW] with bias
    const int mr = wm + (lane >> 2);
    const int cb = hw0 + wn + (lane & 3) * 2;
#pragma unroll
    for (int half = 0; half < 2; half++) {
        int m = mr + half * 8;
        if (m < 27) {
            float bias = off_b[m];
            float* ob = g_off + ((size_t)(bb * 27 + m)) * HW + cb;
#pragma unroll
            for (int nt = 0; nt < 4; nt++) {
                float2 r;
                r.x = acc[nt][half * 2 + 0] + bias;
                r.y = acc[nt][half * 2 + 1] + bias;
                *(float2*)(ob + nt * 8) = r;
            }
        }
    }
}

// ---------------- deformable sampling -> bf16 hi/lo im2col -----------------
__global__ void __launch_bounds__(256)
sample_kernel(const float* __restrict__ feature)
{
    const int tid = threadIdx.x;
    const int w  = tid & 63;
    const int cg = tid >> 6;
    const int h  = blockIdx.x;
    const int k  = blockIdx.y;
    const int b  = blockIdx.z;

    const int hw = h * W + w;
    const int p  = b * HW + hw;
    const size_t obase = (size_t)(b * 27) * HW + hw;

    const float dy = g_off[obase + (size_t)k * HW];
    const float dx = g_off[obase + (size_t)(9 + k) * HW];
    const float mr = g_off[obase + (size_t)(18 + k) * HW];
    const float m  = 1.0f / (1.0f + expf(-mr));

    const int ky = k / 3 - 1, kx = k % 3 - 1;
    const float py = (float)(h + ky) + dy;
    const float px = (float)(w + kx) + dx;

    const float y0f = floorf(py), x0f = floorf(px);
    const float wy = py - y0f, wx = px - x0f;
    const int y0 = (int)y0f, x0 = (int)x0f;
    const int y1 = y0 + 1,   x1 = x0 + 1;

    const bool vy0 = (y0 >= 0) && (y0 < H);
    const bool vy1 = (y1 >= 0) && (y1 < H);
    const bool vx0 = (x0 >= 0) && (x0 < W);
    const bool vx1 = (x1 >= 0) && (x1 < W);

    float w00 = (1.0f - wy) * (1.0f - wx) * ((vy0 && vx0) ? 1.0f : 0.0f);
    float w01 = (1.0f - wy) * wx          * ((vy0 && vx1) ? 1.0f : 0.0f);
    float w10 = wy * (1.0f - wx)          * ((vy1 && vx0) ? 1.0f : 0.0f);
    float w11 = wy * wx                   * ((vy1 && vx1) ? 1.0f : 0.0f);
    w00 *= m; w01 *= m; w10 *= m; w11 *= m;

    const int yc0 = min(max(y0, 0), H - 1);
    const int yc1 = min(max(y1, 0), H - 1);
    const int xc0 = min(max(x0, 0), W - 1);
    const int xc1 = min(max(x1, 0), W - 1);

    const int a00 = yc0 * W + (63 - xc0);
    const int a01 = yc0 * W + (63 - xc1);
    const int a10 = yc1 * W + (63 - xc0);
    const int a11 = yc1 * W + (63 - xc1);

    const float* fb = feature + (size_t)b * CHW + (size_t)(cg * 64) * HW;
    size_t cidx = ((size_t)(cg * 64) * KK + k) * NPIX + p;

#pragma unroll 4
    for (int c = 0; c < 64; c++) {
        float v = w00 * fb[a00] + w01 * fb[a01] + w10 * fb[a10] + w11 * fb[a11];
        __nv_bfloat16 hi = __float2bfloat16(v);
        g_colh[cidx] = hi;
        g_coll[cidx] = __float2bfloat16(v - __bfloat162float(hi));
        fb += HW;
        cidx += (size_t)KK * NPIX;
    }
}

// ---------------- DCN GEMM: mma.sync bf16 split-precision ------------------
#define DCN_NCH 72
#define A_STRIDE 40
#define B_STRIDE 136
#define A_BYTES (128 * A_STRIDE * 2)                 // 10240
#define B_BYTES (32 * B_STRIDE * 2)                  // 8704
#define STAGE_BYTES (2 * A_BYTES + 2 * B_BYTES)      // 37888
#define DCN_SMEM (2 * STAGE_BYTES)                   // 75776

__global__ void __launch_bounds__(256, 1)
dcn_gemm_kernel(float* __restrict__ out)
{
    extern __shared__ char smem[];
    const uint32_t sbase = smem_to_u32(smem);
    const int tid = threadIdx.x;
    const int lane = tid & 31;
    const int wid = tid >> 5;

    const int n0 = blockIdx.x * 128;
    const int m0 = blockIdx.y * 128;
    const int bb = n0 >> 12;
    const int hw0 = n0 & 4095;
    const int wm = (wid >> 2) * 64;
    const int wn = (wid & 3) * 32;

    const __nv_bfloat16* wh = g_wh + (size_t)m0 * CK;
    const __nv_bfloat16* wl = g_wl + (size_t)m0 * CK;

    float acc[4][4][4];
#pragma unroll
    for (int i = 0; i < 4; i++)
#pragma unroll
        for (int j = 0; j < 4; j++)
#pragma unroll
            for (int t = 0; t < 4; t++) acc[i][j][t] = 0.0f;

    auto load_chunk = [&](int st, int kt) {
        const uint32_t s = sbase + st * STAGE_BYTES;
        const int k0 = kt * 32;
#pragma unroll
        for (int i = 0; i < 2; i++) {
            int idx = i * 256 + tid;
            int r = idx >> 2, kseg = idx & 3;
            size_t go = (size_t)r * CK + k0 + kseg * 8;
            uint32_t so = (uint32_t)(r * A_STRIDE + kseg * 8) * 2;
            cp16(s + so, wh + go);
            cp16(s + A_BYTES + so, wl + go);
        }
#pragma unroll
        for (int i = 0; i < 2; i++) {
            int idx = i * 256 + tid;
            int kr = idx >> 4, nseg = idx & 15;
            size_t go = (size_t)(k0 + kr) * NPIX + n0 + nseg * 8;
            uint32_t so = (uint32_t)(kr * B_STRIDE + nseg * 8) * 2;
            cp16(s + 2 * A_BYTES + so, g_colh + go);
            cp16(s + 2 * A_BYTES + B_BYTES + so, g_coll + go);
        }
        CP_COMMIT();
    };

    load_chunk(0, 0);

    for (int kt = 0; kt < DCN_NCH; kt++) {
        const int st = kt & 1;
        if (kt + 1 < DCN_NCH) { load_chunk(st ^ 1, kt + 1); CP_WAIT(1); }
        else                  { CP_WAIT(0); }
        __syncthreads();

        const uint32_t sAh = sbase + st * STAGE_BYTES;
        const uint32_t sAl = sAh + A_BYTES;
        const uint32_t sBh = sAh + 2 * A_BYTES;
        const uint32_t sBl = sBh + B_BYTES;

#pragma unroll
        for (int ks = 0; ks < 2; ks++) {
            uint32_t ah[4][4], al[4][4], bh[4][2], bl[4][2];

            const int arow = wm + (lane & 15);
            const int acol = ks * 16 + ((lane >> 4) << 3);
#pragma unroll
            for (int tm = 0; tm < 4; tm++) {
                uint32_t ao = (uint32_t)((arow + tm * 16) * A_STRIDE + acol) * 2;
                ldsm4(ah[tm], sAh + ao);
                ldsm4(al[tm], sAl + ao);
            }
            const int bkrow = ks * 16 + (lane & 15);
#pragma unroll
            for (int ng = 0; ng < 2; ng++) {
                const int bcol = wn + ng * 16 + ((lane >> 4) << 3);
                uint32_t bo = (uint32_t)(bkrow * B_STRIDE + bcol) * 2;
                uint32_t t[4];
                ldsm4t(t, sBh + bo);
                bh[2*ng][0] = t[0]; bh[2*ng][1] = t[1];
                bh[2*ng+1][0] = t[2]; bh[2*ng+1][1] = t[3];
                ldsm4t(t, sBl + bo);
                bl[2*ng][0] = t[0]; bl[2*ng][1] = t[1];
                bl[2*ng+1][0] = t[2]; bl[2*ng+1][1] = t[3];
            }
#pragma unroll
            for (int tm = 0; tm < 4; tm++)
#pragma unroll
                for (int tn = 0; tn < 4; tn++) {
                    mma16816(acc[tm][tn], ah[tm], bh[tn]);
                    mma16816(acc[tm][tn], ah[tm], bl[tn]);
                    mma16816(acc[tm][tn], al[tm], bh[tn]);
                }
        }
        __syncthreads();
    }

    const int rowl = lane >> 2;
    const int colp = (lane & 3) * 2;
#pragma unroll
    for (int tm = 0; tm < 4; tm++) {
#pragma unroll
        for (int half = 0; half < 2; half++) {
            const int m = m0 + wm + tm * 16 + rowl + half * 8;
            const float add = g_add2[m];
            const float* pr = g_proj + ((size_t)bb * C + m) * HW + hw0 + wn + colp;
            float*       ob = out    + ((size_t)bb * C + m) * HW + hw0 + wn + colp;
#pragma unroll
            for (int tn = 0; tn < 4; tn++) {
                float2 p = *(const float2*)(pr + tn * 8);
                float2 r;
                r.x = fmaxf(acc[tm][tn][half * 2 + 0] + add + p.x, 0.0f);
                r.y = fmaxf(acc[tm][tn][half * 2 + 1] + add + p.y, 0.0f);
                *(float2*)(ob + tn * 8) = r;
            }
        }
    }
}

// ---------------- launch ----------------------------------------------------
extern "C" void kernel_launch(void* const* d_in, const int* in_sizes, int n_in,
                              void* d_out, int out_size)
{
    const float* feature = (const float*)d_in[0];
    const float* p1_w    = (const float*)d_in[1];
    const float* p1_b    = (const float*)d_in[2];
    const float* bn1_g   = (const float*)d_in[3];
    const float* bn1_b   = (const float*)d_in[4];
    const float* bn1_m   = (const float*)d_in[5];
    const float* bn1_v   = (const float*)d_in[6];
    const float* off_w   = (const float*)d_in[7];
    const float* off_b   = (const float*)d_in[8];
    const float* dcn_w   = (const float*)d_in[9];
    const float* dcn_b   = (const float*)d_in[10];
    const float* bn2_g   = (const float*)d_in[11];
    const float* bn2_b   = (const float*)d_in[12];
    const float* bn2_m   = (const float*)d_in[13];
    const float* bn2_v   = (const float*)d_in[14];

    cudaFuncSetAttribute(dcn_gemm_kernel,
                         cudaFuncAttributeMaxDynamicSharedMemorySize, DCN_SMEM);
    cudaFuncSetAttribute(off_gemm_kernel,
                         cudaFuncAttributeMaxDynamicSharedMemorySize, OC_SMEM);

    prep_kernel<<<1, 256>>>(p1_b, bn1_g, bn1_b, bn1_m, bn1_v,
                            dcn_b, bn2_g, bn2_b, bn2_m, bn2_v);
    split_w_kernel<<<(C * CK + 255) / 256, 256>>>(dcn_w);
    prep_offw_kernel<<<(9 * 32 * 512 + 255) / 256, 256>>>(off_w);
    zero_pad_kernel<<<(BATCH * 260 * 512 + 255) / 256, 256>>>();

    proj_gemm_kernel<<<dim3(NPIX / BN, C / BM), 256>>>(p1_w, feature);

    pack_kernel<<<dim3(2, 16, 512), dim3(32, 8)>>>(feature);

    off_gemm_kernel<<<NPIX / 128, 256, OC_SMEM>>>(off_b);

    sample_kernel<<<dim3(H, KK, BATCH), 256>>>(feature);

    dcn_gemm_kernel<<<dim3(NPIX / 128, C / 128), 256, DCN_SMEM>>>((float*)d_out);
}

// round 5
// speedup vs baseline: 2.8813x; 1.1677x over previous
#include <cuda_runtime.h>
#include <cuda_bf16.h>
#include <cuda_fp16.h>
#include <math.h>
#include <stdint.h>

// Problem constants
#define BATCH 8
#define C 256
#define H 64
#define W 64
#define HW 4096
#define NPIX 32768
#define KK 9
#define CK 2304
#define CHW (C*HW)
#define PDIM 66
#define PP (PDIM*PDIM)     // 4356 padded positions per batch

// ---------------- scratch (device globals; no allocation) ----------------
__device__ float g_proj[(size_t)BATCH * CHW];                    // 33.5 MB
__device__ float g_off[(size_t)BATCH * 27 * HW];                 // 3.5 MB
__device__ __half g_colh[(size_t)CK * NPIX];                     // 151 MB (fp16, mask folded)
__device__ __half g_wh[(size_t)C * CK];                          // dcn weights hi (scaled by inv2)
__device__ __half g_wl[(size_t)C * CK];                          // dcn weights lo
__device__ __nv_bfloat16 g_xh[(size_t)BATCH * PP * 512];         // X^T padded hi (bf16)
__device__ __nv_bfloat16 g_xl[(size_t)BATCH * PP * 512];         // lo
__device__ __nv_bfloat16 g_owh[(size_t)9 * 32 * 512];            // offset weights hi
__device__ __nv_bfloat16 g_owl[(size_t)9 * 32 * 512];
__device__ float g_inv1[C], g_add1[C], g_inv2[C], g_add2[C];

// ================= mma.sync / ldmatrix / cp.async helpers =================
__device__ __forceinline__ uint32_t smem_to_u32(const void* p) {
    uint32_t a;
    asm("{ .reg .u64 t; cvta.to.shared.u64 t, %1; cvt.u32.u64 %0, t; }" : "=r"(a) : "l"(p));
    return a;
}
__device__ __forceinline__ void cp16(uint32_t s, const void* g) {
    asm volatile("cp.async.cg.shared.global [%0], [%1], 16;" :: "r"(s), "l"(g));
}
#define CP_COMMIT() asm volatile("cp.async.commit_group;" ::: "memory")
#define CP_WAIT(n)  asm volatile("cp.async.wait_group %0;" :: "n"(n) : "memory")

__device__ __forceinline__ void ldsm4(uint32_t* r, uint32_t addr) {
    asm volatile("ldmatrix.sync.aligned.m8n8.x4.shared.b16 {%0,%1,%2,%3}, [%4];"
        : "=r"(r[0]), "=r"(r[1]), "=r"(r[2]), "=r"(r[3]) : "r"(addr));
}
__device__ __forceinline__ void ldsm4t(uint32_t* r, uint32_t addr) {
    asm volatile("ldmatrix.sync.aligned.m8n8.x4.trans.shared.b16 {%0,%1,%2,%3}, [%4];"
        : "=r"(r[0]), "=r"(r[1]), "=r"(r[2]), "=r"(r[3]) : "r"(addr));
}
__device__ __forceinline__ uint32_t lds32(uint32_t addr) {
    uint32_t v;
    asm volatile("ld.shared.b32 %0, [%1];" : "=r"(v) : "r"(addr));
    return v;
}
// bf16 MMA (offset conv path)
__device__ __forceinline__ void mma_bf(float* c, const uint32_t* a, const uint32_t* b) {
    asm volatile("mma.sync.aligned.m16n8k16.row.col.f32.bf16.bf16.f32 "
        "{%0,%1,%2,%3}, {%4,%5,%6,%7}, {%8,%9}, {%0,%1,%2,%3};"
        : "+f"(c[0]), "+f"(c[1]), "+f"(c[2]), "+f"(c[3])
        : "r"(a[0]), "r"(a[1]), "r"(a[2]), "r"(a[3]), "r"(b[0]), "r"(b[1]));
}
// fp16 MMA (dcn path)
__device__ __forceinline__ void mma_fp(float* c, const uint32_t* a, const uint32_t* b) {
    asm volatile("mma.sync.aligned.m16n8k16.row.col.f32.f16.f16.f32 "
        "{%0,%1,%2,%3}, {%4,%5,%6,%7}, {%8,%9}, {%0,%1,%2,%3};"
        : "+f"(c[0]), "+f"(c[1]), "+f"(c[2]), "+f"(c[3])
        : "r"(a[0]), "r"(a[1]), "r"(a[2]), "r"(a[3]), "r"(b[0]), "r"(b[1]));
}

// ---------------- prep -----------------------------------------------------
__global__ void prep_kernel(const float* __restrict__ p1_b,
                            const float* __restrict__ bn1_g, const float* __restrict__ bn1_b,
                            const float* __restrict__ bn1_m, const float* __restrict__ bn1_v,
                            const float* __restrict__ dcn_b,
                            const float* __restrict__ bn2_g, const float* __restrict__ bn2_b,
                            const float* __restrict__ bn2_m, const float* __restrict__ bn2_v)
{
    int o = threadIdx.x;
    if (o < C) {
        float inv1 = bn1_g[o] / sqrtf(bn1_v[o] + 1e-5f);
        g_inv1[o] = inv1;
        g_add1[o] = bn1_b[o] - bn1_m[o] * inv1 + p1_b[o] * inv1;
        float inv2 = bn2_g[o] / sqrtf(bn2_v[o] + 1e-5f);
        g_inv2[o] = inv2;
        g_add2[o] = bn2_b[o] - bn2_m[o] * inv2 + dcn_b[o] * inv2;
    }
}

// split dcn weights (scaled by inv2) into fp16 hi/lo
__global__ void split_w_kernel(const float* __restrict__ dcn_w)
{
    int idx = blockIdx.x * 256 + threadIdx.x;
    if (idx < C * CK) {
        int o = idx / CK;
        float v = dcn_w[idx] * g_inv2[o];
        __half hi = __float2half(v);
        float lo = v - __half2float(hi);
        g_wh[idx] = hi;
        g_wl[idx] = __float2half(lo);
    }
}

// repack offset weights: off_w[27][512][3][3] -> g_owh/l [tap(9)][32][512]
__global__ void prep_offw_kernel(const float* __restrict__ off_w)
{
    int idx = blockIdx.x * 256 + threadIdx.x;
    if (idx < 9 * 32 * 512) {
        int t = idx >> 14;            // tap
        int r = (idx >> 9) & 31;      // output row (27 used)
        int c = idx & 511;            // input channel
        float v = 0.0f;
        if (r < 27) {
            int kh = t / 3, kw = t % 3;
            v = off_w[((size_t)(r * 512 + c) * 3 + kh) * 3 + kw];
        }
        __nv_bfloat16 hi = __float2bfloat16(v);
        g_owh[idx] = hi;
        g_owl[idx] = __float2bfloat16(v - __bfloat162float(hi));
    }
}

// zero the padding ring of g_xh/g_xl
__global__ void zero_pad_kernel()
{
    int idx = blockIdx.x * 256 + threadIdx.x;
    if (idx < BATCH * 260 * 512) {
        int c = idx & 511;
        int rest = idx >> 9;
        int pos = rest % 260;
        int b = rest / 260;
        int yp, xp;
        if (pos < 66)       { yp = 0;  xp = pos; }
        else if (pos < 132) { yp = 65; xp = pos - 66; }
        else {
            int i = pos - 132;
            yp = 1 + (i >> 1);
            xp = (i & 1) * 65;
        }
        size_t a = ((size_t)b * PP + yp * PDIM + xp) * 512 + c;
        g_xh[a] = __float2bfloat16(0.0f);
        g_xl[a] = __float2bfloat16(0.0f);
    }
}

// pack concat(flip(feature), proj) transposed -> X^T[b][pad pos][512] hi/lo
__global__ void __launch_bounds__(256)
pack_kernel(const float* __restrict__ feature)
{
    __shared__ float tile[32][33];
    const int tx = threadIdx.x, ty = threadIdx.y;
    const int b = blockIdx.z >> 6;
    const int y = blockIdx.z & 63;
    const int x0 = blockIdx.x * 32;
    const int c0 = blockIdx.y * 32;

#pragma unroll
    for (int j = 0; j < 4; j++) {
        int c = c0 + ty + j * 8;
        int x = x0 + tx;
        float v;
        if (c < 256) v = feature[((size_t)(b * 256 + c) * 64 + y) * 64 + (63 - x)];
        else         v = g_proj[((size_t)(b * 256 + (c - 256)) * 64 + y) * 64 + x];
        tile[ty + j * 8][tx] = v;
    }
    __syncthreads();
#pragma unroll
    for (int j = 0; j < 4; j++) {
        int xl = ty + j * 8;
        float v = tile[tx][xl];
        size_t a = ((size_t)b * PP + (y + 1) * PDIM + (x0 + xl + 1)) * 512 + c0 + tx;
        __nv_bfloat16 hi = __float2bfloat16(v);
        g_xh[a] = hi;
        g_xl[a] = __float2bfloat16(v - __bfloat162float(hi));
    }
}

// ---------------- proj GEMM (fp32) -----------------------------------------
#define BM 128
#define BN 128
#define BKT 16
#define TM 8
#define TN 8

__global__ void __launch_bounds__(256)
proj_gemm_kernel(const float* __restrict__ A, const float* __restrict__ Bsrc)
{
    __shared__ float sA[BKT][BM + 4];
    __shared__ float sB[BKT][BN + 4];

    const int tid = threadIdx.x;
    const int pb0 = blockIdx.x * BN;
    const int m0  = blockIdx.y * BM;
    const int bb  = pb0 >> 12;
    const int hw0 = pb0 & 4095;

    const float* Bbase = Bsrc + (size_t)bb * CHW + hw0;
    const int strideK = HW;

    const int rowl = (tid >> 4) * TM;
    const int coll = (tid & 15) * TN;

    float acc[TM][TN];
#pragma unroll
    for (int i = 0; i < TM; i++)
#pragma unroll
        for (int j = 0; j < TN; j++) acc[i][j] = 0.0f;

    const int Kdim = 256;
    for (int kt = 0; kt < Kdim / BKT; kt++) {
        const int k0 = kt * BKT;
#pragma unroll
        for (int l = 0; l < 2; l++) {
            int f = tid + l * 256;
            int row = f >> 2;
            int jc  = (f & 3) * 4;
            float4 v = *(const float4*)(A + (size_t)(m0 + row) * Kdim + k0 + jc);
            sA[jc + 0][row] = v.x; sA[jc + 1][row] = v.y;
            sA[jc + 2][row] = v.z; sA[jc + 3][row] = v.w;
        }
#pragma unroll
        for (int l = 0; l < 2; l++) {
            int f = tid + l * 256;
            int kk = f >> 5;
            int jc = (f & 31) * 4;
            float4 v = *(const float4*)(Bbase + (size_t)(k0 + kk) * strideK + jc);
            *(float4*)&sB[kk][jc] = v;
        }
        __syncthreads();
#pragma unroll
        for (int kk = 0; kk < BKT; kk++) {
            float a[TM], b[TN];
#pragma unroll
            for (int i = 0; i < TM; i++) a[i] = sA[kk][rowl + i];
#pragma unroll
            for (int j = 0; j < TN; j++) b[j] = sB[kk][coll + j];
#pragma unroll
            for (int i = 0; i < TM; i++)
#pragma unroll
                for (int j = 0; j < TN; j++) acc[i][j] += a[i] * b[j];
        }
        __syncthreads();
    }

    float* ob = g_proj + (size_t)bb * CHW + hw0;
#pragma unroll
    for (int i = 0; i < TM; i++) {
        int o = m0 + rowl + i;
        float inv = g_inv1[o], add = g_add1[o];
#pragma unroll
        for (int j = 0; j < TN; j++)
            ob[(size_t)o * HW + coll + j] = acc[i][j] * inv + add;
    }
}

// ---------------- offset conv as tensor-core GEMM (v2: N=256, 8 chains) ----
// M=32 (27 used), N=256 pixels (4 image rows), K = 9 taps x 512 channels.
// B slab: 396 padded-position rows x 32 channels, shared across all 9 taps.
#define OC_ROWS 396
#define OC_BSTR 40
#define OC_ASTR 40
#define OC_B_BYTES (OC_ROWS * OC_BSTR * 2)         // 31680
#define OC_A_BYTES (9 * 32 * OC_ASTR * 2)          // 23040
#define OC_STAGE (2 * OC_B_BYTES + 2 * OC_A_BYTES) // 109440
#define OC_SMEM (2 * OC_STAGE)                     // 218880

__global__ void __launch_bounds__(256, 1)
off_gemm_kernel(const float* __restrict__ off_b)
{
    extern __shared__ char smem[];
    const uint32_t sbase = smem_to_u32(smem);
    const int tid = threadIdx.x;
    const int lane = tid & 31;
    const int wid = tid >> 5;

    const int n0 = blockIdx.x * 256;
    const int bb = n0 >> 12;
    const int hw0 = n0 & 4095;
    const int h0 = hw0 >> 6;

    const int wm = (wid >> 2) * 16;   // warp m offset (0/16)
    const int wn = (wid & 3) * 64;    // warp n offset (0/64/128/192)

    const size_t pbase = (size_t)bb * PP + h0 * PDIM;

    // per-thread padded-row bases for the 8 n8 tiles
    int rowb[8];
#pragma unroll
    for (int nt = 0; nt < 8; nt++) {
        int nl = wn + nt * 8 + (lane >> 2);
        rowb[nt] = ((nl >> 6) + 1) * PDIM + (nl & 63) + 1;
    }
    const int am = wm + (lane & 15);
    const int acol2 = (lane >> 4) << 3;

    float acc[8][4];
#pragma unroll
    for (int i = 0; i < 8; i++)
#pragma unroll
        for (int j = 0; j < 4; j++) acc[i][j] = 0.0f;

    auto load_chunk = [&](int st, int kc) {
        const uint32_t s = sbase + st * OC_STAGE;
        const int k0 = kc * 32;
        // B: 396 rows x 32ch (hi+lo)
#pragma unroll
        for (int i = 0; i < 7; i++) {
            int idx = i * 256 + tid;
            if (idx < 1584) {
                int r = idx >> 2, c4 = idx & 3;
                size_t go = (pbase + r) * 512 + k0 + c4 * 8;
                uint32_t so = (uint32_t)(r * OC_BSTR + c4 * 8) * 2;
                cp16(s + so, g_xh + go);
                cp16(s + OC_B_BYTES + so, g_xl + go);
            }
        }
        // A: 288 rows (tap*32+m) x 32ch
#pragma unroll
        for (int i = 0; i < 5; i++) {
            int idx = i * 256 + tid;
            if (idx < 1152) {
                int r = idx >> 2, c4 = idx & 3;
                size_t go = (size_t)r * 512 + k0 + c4 * 8;
                uint32_t so = (uint32_t)(r * OC_ASTR + c4 * 8) * 2;
                cp16(s + 2 * OC_B_BYTES + so, g_owh + go);
                cp16(s + 2 * OC_B_BYTES + OC_A_BYTES + so, g_owl + go);
            }
        }
        CP_COMMIT();
    };

    const int stap[9] = {-PDIM-1, -PDIM, -PDIM+1, -1, 0, 1, PDIM-1, PDIM, PDIM+1};

    load_chunk(0, 0);

    for (int kc = 0; kc < 16; kc++) {
        const int st = kc & 1;
        if (kc + 1 < 16) { load_chunk(st ^ 1, kc + 1); CP_WAIT(1); }
        else             { CP_WAIT(0); }
        __syncthreads();

        const uint32_t sBh = sbase + st * OC_STAGE;
        const uint32_t sBl = sBh + OC_B_BYTES;
        const uint32_t sAh = sBh + 2 * OC_B_BYTES;
        const uint32_t sAl = sAh + OC_A_BYTES;

#pragma unroll
        for (int tap = 0; tap < 9; tap++) {
            const int s_t = stap[tap];
#pragma unroll
            for (int ks = 0; ks < 2; ks++) {
                uint32_t ah[4], al[4];
                uint32_t ao = (uint32_t)((tap * 32 + am) * OC_ASTR + ks * 16 + acol2) * 2;
                ldsm4(ah, sAh + ao);
                ldsm4(al, sAl + ao);
#pragma unroll
                for (int nt = 0; nt < 8; nt++) {
                    int row = rowb[nt] + s_t;
                    uint32_t base = (uint32_t)(row * OC_BSTR + ks * 16 + (lane & 3) * 2) * 2;
                    uint32_t bh[2], bl[2];
                    bh[0] = lds32(sBh + base);
                    bh[1] = lds32(sBh + base + 16);
                    bl[0] = lds32(sBl + base);
                    bl[1] = lds32(sBl + base + 16);
                    mma_bf(acc[nt], ah, bh);
                    mma_bf(acc[nt], ah, bl);
                    mma_bf(acc[nt], al, bh);
                }
            }
        }
        __syncthreads();
    }

    // epilogue: write rows <27 of g_off[b][27][HW] with bias
    const int mr = wm + (lane >> 2);
    const int cb = hw0 + wn + (lane & 3) * 2;
#pragma unroll
    for (int half = 0; half < 2; half++) {
        int m = mr + half * 8;
        if (m < 27) {
            float bias = off_b[m];
            float* ob = g_off + ((size_t)(bb * 27 + m)) * HW + cb;
#pragma unroll
            for (int nt = 0; nt < 8; nt++) {
                float2 r;
                r.x = acc[nt][half * 2 + 0] + bias;
                r.y = acc[nt][half * 2 + 1] + bias;
                *(float2*)(ob + nt * 8) = r;
            }
        }
    }
}

// ---------------- deformable sampling -> fp16 im2col (mask folded) ---------
__global__ void __launch_bounds__(256)
sample_kernel(const float* __restrict__ feature)
{
    const int tid = threadIdx.x;
    const int w  = tid & 63;
    const int cg = tid >> 6;
    const int h  = blockIdx.x;
    const int k  = blockIdx.y;
    const int b  = blockIdx.z;

    const int hw = h * W + w;
    const int p  = b * HW + hw;
    const size_t obase = (size_t)(b * 27) * HW + hw;

    const float dy = g_off[obase + (size_t)k * HW];
    const float dx = g_off[obase + (size_t)(9 + k) * HW];
    const float mr = g_off[obase + (size_t)(18 + k) * HW];
    const float m  = 1.0f / (1.0f + expf(-mr));

    const int ky = k / 3 - 1, kx = k % 3 - 1;
    const float py = (float)(h + ky) + dy;
    const float px = (float)(w + kx) + dx;

    const float y0f = floorf(py), x0f = floorf(px);
    const float wy = py - y0f, wx = px - x0f;
    const int y0 = (int)y0f, x0 = (int)x0f;
    const int y1 = y0 + 1,   x1 = x0 + 1;

    const bool vy0 = (y0 >= 0) && (y0 < H);
    const bool vy1 = (y1 >= 0) && (y1 < H);
    const bool vx0 = (x0 >= 0) && (x0 < W);
    const bool vx1 = (x1 >= 0) && (x1 < W);

    float w00 = (1.0f - wy) * (1.0f - wx) * ((vy0 && vx0) ? 1.0f : 0.0f);
    float w01 = (1.0f - wy) * wx          * ((vy0 && vx1) ? 1.0f : 0.0f);
    float w10 = wy * (1.0f - wx)          * ((vy1 && vx0) ? 1.0f : 0.0f);
    float w11 = wy * wx                   * ((vy1 && vx1) ? 1.0f : 0.0f);
    w00 *= m; w01 *= m; w10 *= m; w11 *= m;

    const int yc0 = min(max(y0, 0), H - 1);
    const int yc1 = min(max(y1, 0), H - 1);
    const int xc0 = min(max(x0, 0), W - 1);
    const int xc1 = min(max(x1, 0), W - 1);

    const int a00 = yc0 * W + (63 - xc0);
    const int a01 = yc0 * W + (63 - xc1);
    const int a10 = yc1 * W + (63 - xc0);
    const int a11 = yc1 * W + (63 - xc1);

    const float* fb = feature + (size_t)b * CHW + (size_t)(cg * 64) * HW;
    size_t cidx = ((size_t)(cg * 64) * KK + k) * NPIX + p;

#pragma unroll 4
    for (int c = 0; c < 64; c++) {
        float v = w00 * fb[a00] + w01 * fb[a01] + w10 * fb[a10] + w11 * fb[a11];
        g_colh[cidx] = __float2half(v);
        fb += HW;
        cidx += (size_t)KK * NPIX;
    }
}

// ---------------- DCN GEMM: mma.sync fp16, 2-term (wh+wl)·colh -------------
#define DCN_NCH 72
#define A_STRIDE 40
#define B_STRIDE 136
#define A_BYTES (128 * A_STRIDE * 2)                 // 10240
#define B_BYTES (32 * B_STRIDE * 2)                  // 8704
#define STAGE_BYTES (2 * A_BYTES + B_BYTES)          // 29184
#define DCN_SMEM (2 * STAGE_BYTES)                   // 58368

__global__ void __launch_bounds__(256, 1)
dcn_gemm_kernel(float* __restrict__ out)
{
    extern __shared__ char smem[];
    const uint32_t sbase = smem_to_u32(smem);
    const int tid = threadIdx.x;
    const int lane = tid & 31;
    const int wid = tid >> 5;

    const int n0 = blockIdx.x * 128;
    const int m0 = blockIdx.y * 128;
    const int bb = n0 >> 12;
    const int hw0 = n0 & 4095;
    const int wm = (wid >> 2) * 64;
    const int wn = (wid & 3) * 32;

    const __half* wh = g_wh + (size_t)m0 * CK;
    const __half* wl = g_wl + (size_t)m0 * CK;

    float acc[4][4][4];
#pragma unroll
    for (int i = 0; i < 4; i++)
#pragma unroll
        for (int j = 0; j < 4; j++)
#pragma unroll
            for (int t = 0; t < 4; t++) acc[i][j][t] = 0.0f;

    auto load_chunk = [&](int st, int kt) {
        const uint32_t s = sbase + st * STAGE_BYTES;
        const int k0 = kt * 32;
#pragma unroll
        for (int i = 0; i < 2; i++) {
            int idx = i * 256 + tid;
            int r = idx >> 2, kseg = idx & 3;
            size_t go = (size_t)r * CK + k0 + kseg * 8;
            uint32_t so = (uint32_t)(r * A_STRIDE + kseg * 8) * 2;
            cp16(s + so, wh + go);
            cp16(s + A_BYTES + so, wl + go);
        }
#pragma unroll
        for (int i = 0; i < 2; i++) {
            int idx = i * 256 + tid;
            int kr = idx >> 4, nseg = idx & 15;
            size_t go = (size_t)(k0 + kr) * NPIX + n0 + nseg * 8;
            uint32_t so = (uint32_t)(kr * B_STRIDE + nseg * 8) * 2;
            cp16(s + 2 * A_BYTES + so, g_colh + go);
        }
        CP_COMMIT();
    };

    load_chunk(0, 0);

    for (int kt = 0; kt < DCN_NCH; kt++) {
        const int st = kt & 1;
        if (kt + 1 < DCN_NCH) { load_chunk(st ^ 1, kt + 1); CP_WAIT(1); }
        else                  { CP_WAIT(0); }
        __syncthreads();

        const uint32_t sAh = sbase + st * STAGE_BYTES;
        const uint32_t sAl = sAh + A_BYTES;
        const uint32_t sB  = sAh + 2 * A_BYTES;

#pragma unroll
        for (int ks = 0; ks < 2; ks++) {
            uint32_t ah[4][4], al[4][4], bf[4][2];

            const int arow = wm + (lane & 15);
            const int acol = ks * 16 + ((lane >> 4) << 3);
#pragma unroll
            for (int tm = 0; tm < 4; tm++) {
                uint32_t ao = (uint32_t)((arow + tm * 16) * A_STRIDE + acol) * 2;
                ldsm4(ah[tm], sAh + ao);
                ldsm4(al[tm], sAl + ao);
            }
            const int bkrow = ks * 16 + (lane & 15);
#pragma unroll
            for (int ng = 0; ng < 2; ng++) {
                const int bcol = wn + ng * 16 + ((lane >> 4) << 3);
                uint32_t bo = (uint32_t)(bkrow * B_STRIDE + bcol) * 2;
                uint32_t t[4];
                ldsm4t(t, sB + bo);
                bf[2*ng][0] = t[0]; bf[2*ng][1] = t[1];
                bf[2*ng+1][0] = t[2]; bf[2*ng+1][1] = t[3];
            }
#pragma unroll
            for (int tm = 0; tm < 4; tm++)
#pragma unroll
                for (int tn = 0; tn < 4; tn++) {
                    mma_fp(acc[tm][tn], ah[tm], bf[tn]);
                    mma_fp(acc[tm][tn], al[tm], bf[tn]);
                }
        }
        __syncthreads();
    }

    const int rowl = lane >> 2;
    const int colp = (lane & 3) * 2;
#pragma unroll
    for (int tm = 0; tm < 4; tm++) {
#pragma unroll
        for (int half = 0; half < 2; half++) {
            const int m = m0 + wm + tm * 16 + rowl + half * 8;
            const float add = g_add2[m];
            const float* pr = g_proj + ((size_t)bb * C + m) * HW + hw0 + wn + colp;
            float*       ob = out    + ((size_t)bb * C + m) * HW + hw0 + wn + colp;
#pragma unroll
            for (int tn = 0; tn < 4; tn++) {
                float2 p = *(const float2*)(pr + tn * 8);
                float2 r;
                r.x = fmaxf(acc[tm][tn][half * 2 + 0] + add + p.x, 0.0f);
                r.y = fmaxf(acc[tm][tn][half * 2 + 1] + add + p.y, 0.0f);
                *(float2*)(ob + tn * 8) = r;
            }
        }
    }
}

// ---------------- launch ----------------------------------------------------
extern "C" void kernel_launch(void* const* d_in, const int* in_sizes, int n_in,
                              void* d_out, int out_size)
{
    const float* feature = (const float*)d_in[0];
    const float* p1_w    = (const float*)d_in[1];
    const float* p1_b    = (const float*)d_in[2];
    const float* bn1_g   = (const float*)d_in[3];
    const float* bn1_b   = (const float*)d_in[4];
    const float* bn1_m   = (const float*)d_in[5];
    const float* bn1_v   = (const float*)d_in[6];
    const float* off_w   = (const float*)d_in[7];
    const float* off_b   = (const float*)d_in[8];
    const float* dcn_w   = (const float*)d_in[9];
    const float* dcn_b   = (const float*)d_in[10];
    const float* bn2_g   = (const float*)d_in[11];
    const float* bn2_b   = (const float*)d_in[12];
    const float* bn2_m   = (const float*)d_in[13];
    const float* bn2_v   = (const float*)d_in[14];

    cudaFuncSetAttribute(dcn_gemm_kernel,
                         cudaFuncAttributeMaxDynamicSharedMemorySize, DCN_SMEM);
    cudaFuncSetAttribute(off_gemm_kernel,
                         cudaFuncAttributeMaxDynamicSharedMemorySize, OC_SMEM);

    prep_kernel<<<1, 256>>>(p1_b, bn1_g, bn1_b, bn1_m, bn1_v,
                            dcn_b, bn2_g, bn2_b, bn2_m, bn2_v);
    split_w_kernel<<<(C * CK + 255) / 256, 256>>>(dcn_w);
    prep_offw_kernel<<<(9 * 32 * 512 + 255) / 256, 256>>>(off_w);
    zero_pad_kernel<<<(BATCH * 260 * 512 + 255) / 256, 256>>>();

    proj_gemm_kernel<<<dim3(NPIX / BN, C / BM), 256>>>(p1_w, feature);

    pack_kernel<<<dim3(2, 16, 512), dim3(32, 8)>>>(feature);

    off_gemm_kernel<<<NPIX / 256, 256, OC_SMEM>>>(off_b);

    sample_kernel<<<dim3(H, KK, BATCH), 256>>>(feature);

    dcn_gemm_kernel<<<dim3(NPIX / 128, C / 128), 256, DCN_SMEM>>>((float*)d_out);
}

// round 6
// speedup vs baseline: 3.0131x; 1.0458x over previous
#include <cuda_runtime.h>
#include <cuda_bf16.h>
#include <cuda_fp16.h>
#include <math.h>
#include <stdint.h>

// Problem constants
#define BATCH 8
#define C 256
#define H 64
#define W 64
#define HW 4096
#define NPIX 32768
#define KK 9
#define CK 2304
#define CHW (C*HW)
#define PDIM 66
#define PP (PDIM*PDIM)     // 4356 padded positions per batch

// ---------------- scratch (device globals; no allocation) ----------------
__device__ float g_proj[(size_t)BATCH * CHW];                    // 33.5 MB
__device__ float g_off[(size_t)BATCH * 27 * HW];                 // 3.5 MB
__device__ __half g_colh[(size_t)CK * NPIX];                     // 151 MB (fp16, mask folded)
__device__ __half g_wh[(size_t)C * CK];                          // dcn weights hi (scaled by inv2)
__device__ __half g_wl[(size_t)C * CK];                          // dcn weights lo
__device__ __half g_xh[(size_t)BATCH * PP * 512];                // X^T padded (fp16 single)
__device__ __half g_owh[(size_t)9 * 32 * 512];                   // offset weights hi (fp16)
__device__ __half g_owl[(size_t)9 * 32 * 512];                   // offset weights lo
__device__ float g_inv1[C], g_add1[C], g_inv2[C], g_add2[C];

// ================= mma.sync / ldmatrix / cp.async helpers =================
__device__ __forceinline__ uint32_t smem_to_u32(const void* p) {
    uint32_t a;
    asm("{ .reg .u64 t; cvta.to.shared.u64 t, %1; cvt.u32.u64 %0, t; }" : "=r"(a) : "l"(p));
    return a;
}
__device__ __forceinline__ void cp16(uint32_t s, const void* g) {
    asm volatile("cp.async.cg.shared.global [%0], [%1], 16;" :: "r"(s), "l"(g));
}
#define CP_COMMIT() asm volatile("cp.async.commit_group;" ::: "memory")
#define CP_WAIT(n)  asm volatile("cp.async.wait_group %0;" :: "n"(n) : "memory")

__device__ __forceinline__ void ldsm4(uint32_t* r, uint32_t addr) {
    asm volatile("ldmatrix.sync.aligned.m8n8.x4.shared.b16 {%0,%1,%2,%3}, [%4];"
        : "=r"(r[0]), "=r"(r[1]), "=r"(r[2]), "=r"(r[3]) : "r"(addr));
}
__device__ __forceinline__ void ldsm4t(uint32_t* r, uint32_t addr) {
    asm volatile("ldmatrix.sync.aligned.m8n8.x4.trans.shared.b16 {%0,%1,%2,%3}, [%4];"
        : "=r"(r[0]), "=r"(r[1]), "=r"(r[2]), "=r"(r[3]) : "r"(addr));
}
__device__ __forceinline__ uint32_t lds32(uint32_t addr) {
    uint32_t v;
    asm volatile("ld.shared.b32 %0, [%1];" : "=r"(v) : "r"(addr));
    return v;
}
// fp16 MMA
__device__ __forceinline__ void mma_fp(float* c, const uint32_t* a, const uint32_t* b) {
    asm volatile("mma.sync.aligned.m16n8k16.row.col.f32.f16.f16.f32 "
        "{%0,%1,%2,%3}, {%4,%5,%6,%7}, {%8,%9}, {%0,%1,%2,%3};"
        : "+f"(c[0]), "+f"(c[1]), "+f"(c[2]), "+f"(c[3])
        : "r"(a[0]), "r"(a[1]), "r"(a[2]), "r"(a[3]), "r"(b[0]), "r"(b[1]));
}

// ---------------- prep -----------------------------------------------------
__global__ void prep_kernel(const float* __restrict__ p1_b,
                            const float* __restrict__ bn1_g, const float* __restrict__ bn1_b,
                            const float* __restrict__ bn1_m, const float* __restrict__ bn1_v,
                            const float* __restrict__ dcn_b,
                            const float* __restrict__ bn2_g, const float* __restrict__ bn2_b,
                            const float* __restrict__ bn2_m, const float* __restrict__ bn2_v)
{
    int o = threadIdx.x;
    if (o < C) {
        float inv1 = bn1_g[o] / sqrtf(bn1_v[o] + 1e-5f);
        g_inv1[o] = inv1;
        g_add1[o] = bn1_b[o] - bn1_m[o] * inv1 + p1_b[o] * inv1;
        float inv2 = bn2_g[o] / sqrtf(bn2_v[o] + 1e-5f);
        g_inv2[o] = inv2;
        g_add2[o] = bn2_b[o] - bn2_m[o] * inv2 + dcn_b[o] * inv2;
    }
}

// split dcn weights (scaled by inv2) into fp16 hi/lo
__global__ void split_w_kernel(const float* __restrict__ dcn_w)
{
    int idx = blockIdx.x * 256 + threadIdx.x;
    if (idx < C * CK) {
        int o = idx / CK;
        float v = dcn_w[idx] * g_inv2[o];
        __half hi = __float2half(v);
        float lo = v - __half2float(hi);
        g_wh[idx] = hi;
        g_wl[idx] = __float2half(lo);
    }
}

// repack offset weights: off_w[27][512][3][3] -> g_owh/l [tap(9)][32][512] fp16 hi/lo
__global__ void prep_offw_kernel(const float* __restrict__ off_w)
{
    int idx = blockIdx.x * 256 + threadIdx.x;
    if (idx < 9 * 32 * 512) {
        int t = idx >> 14;            // tap
        int r = (idx >> 9) & 31;      // output row (27 used)
        int c = idx & 511;            // input channel
        float v = 0.0f;
        if (r < 27) {
            int kh = t / 3, kw = t % 3;
            v = off_w[((size_t)(r * 512 + c) * 3 + kh) * 3 + kw];
        }
        __half hi = __float2half(v);
        g_owh[idx] = hi;
        g_owl[idx] = __float2half(v - __half2float(hi));
    }
}

// zero the padding ring of g_xh
__global__ void zero_pad_kernel()
{
    int idx = blockIdx.x * 256 + threadIdx.x;
    if (idx < BATCH * 260 * 512) {
        int c = idx & 511;
        int rest = idx >> 9;
        int pos = rest % 260;
        int b = rest / 260;
        int yp, xp;
        if (pos < 66)       { yp = 0;  xp = pos; }
        else if (pos < 132) { yp = 65; xp = pos - 66; }
        else {
            int i = pos - 132;
            yp = 1 + (i >> 1);
            xp = (i & 1) * 65;
        }
        size_t a = ((size_t)b * PP + yp * PDIM + xp) * 512 + c;
        g_xh[a] = __float2half(0.0f);
    }
}

// pack concat(flip(feature), proj) transposed -> X^T[b][pad pos][512] fp16
__global__ void __launch_bounds__(256)
pack_kernel(const float* __restrict__ feature)
{
    __shared__ float tile[32][33];
    const int tx = threadIdx.x, ty = threadIdx.y;
    const int b = blockIdx.z >> 6;
    const int y = blockIdx.z & 63;
    const int x0 = blockIdx.x * 32;
    const int c0 = blockIdx.y * 32;

#pragma unroll
    for (int j = 0; j < 4; j++) {
        int c = c0 + ty + j * 8;
        int x = x0 + tx;
        float v;
        if (c < 256) v = feature[((size_t)(b * 256 + c) * 64 + y) * 64 + (63 - x)];
        else         v = g_proj[((size_t)(b * 256 + (c - 256)) * 64 + y) * 64 + x];
        tile[ty + j * 8][tx] = v;
    }
    __syncthreads();
#pragma unroll
    for (int j = 0; j < 4; j++) {
        int xl = ty + j * 8;
        float v = tile[tx][xl];
        size_t a = ((size_t)b * PP + (y + 1) * PDIM + (x0 + xl + 1)) * 512 + c0 + tx;
        g_xh[a] = __float2half(v);
    }
}

// ---------------- proj GEMM (fp32) -----------------------------------------
#define BM 128
#define BN 128
#define BKT 16
#define TM 8
#define TN 8

__global__ void __launch_bounds__(256)
proj_gemm_kernel(const float* __restrict__ A, const float* __restrict__ Bsrc)
{
    __shared__ float sA[BKT][BM + 4];
    __shared__ float sB[BKT][BN + 4];

    const int tid = threadIdx.x;
    const int pb0 = blockIdx.x * BN;
    const int m0  = blockIdx.y * BM;
    const int bb  = pb0 >> 12;
    const int hw0 = pb0 & 4095;

    const float* Bbase = Bsrc + (size_t)bb * CHW + hw0;
    const int strideK = HW;

    const int rowl = (tid >> 4) * TM;
    const int coll = (tid & 15) * TN;

    float acc[TM][TN];
#pragma unroll
    for (int i = 0; i < TM; i++)
#pragma unroll
        for (int j = 0; j < TN; j++) acc[i][j] = 0.0f;

    const int Kdim = 256;
    for (int kt = 0; kt < Kdim / BKT; kt++) {
        const int k0 = kt * BKT;
#pragma unroll
        for (int l = 0; l < 2; l++) {
            int f = tid + l * 256;
            int row = f >> 2;
            int jc  = (f & 3) * 4;
            float4 v = *(const float4*)(A + (size_t)(m0 + row) * Kdim + k0 + jc);
            sA[jc + 0][row] = v.x; sA[jc + 1][row] = v.y;
            sA[jc + 2][row] = v.z; sA[jc + 3][row] = v.w;
        }
#pragma unroll
        for (int l = 0; l < 2; l++) {
            int f = tid + l * 256;
            int kk = f >> 5;
            int jc = (f & 31) * 4;
            float4 v = *(const float4*)(Bbase + (size_t)(k0 + kk) * strideK + jc);
            *(float4*)&sB[kk][jc] = v;
        }
        __syncthreads();
#pragma unroll
        for (int kk = 0; kk < BKT; kk++) {
            float a[TM], b[TN];
#pragma unroll
            for (int i = 0; i < TM; i++) a[i] = sA[kk][rowl + i];
#pragma unroll
            for (int j = 0; j < TN; j++) b[j] = sB[kk][coll + j];
#pragma unroll
            for (int i = 0; i < TM; i++)
#pragma unroll
                for (int j = 0; j < TN; j++) acc[i][j] += a[i] * b[j];
        }
        __syncthreads();
    }

    float* ob = g_proj + (size_t)bb * CHW + hw0;
#pragma unroll
    for (int i = 0; i < TM; i++) {
        int o = m0 + rowl + i;
        float inv = g_inv1[o], add = g_add1[o];
#pragma unroll
        for (int j = 0; j < TN; j++)
            ob[(size_t)o * HW + coll + j] = acc[i][j] * inv + add;
    }
}

// ---------------- offset conv as tensor-core GEMM (fp16 2-term) ------------
// M=32 (27 used), N=256 pixels (4 image rows), K = 9 taps x 512 channels.
// B slab: 396 padded-position rows x 32 channels fp16 (single), shared by taps.
#define OC_ROWS 396
#define OC_BSTR 40
#define OC_ASTR 40
#define OC_B_BYTES (OC_ROWS * OC_BSTR * 2)         // 31680
#define OC_A_BYTES (9 * 32 * OC_ASTR * 2)          // 23040 per component
#define OC_STAGE (OC_B_BYTES + 2 * OC_A_BYTES)     // 77760
#define OC_SMEM (2 * OC_STAGE)                     // 155520

__global__ void __launch_bounds__(256, 1)
off_gemm_kernel(const float* __restrict__ off_b)
{
    extern __shared__ char smem[];
    const uint32_t sbase = smem_to_u32(smem);
    const int tid = threadIdx.x;
    const int lane = tid & 31;
    const int wid = tid >> 5;

    const int n0 = blockIdx.x * 256;
    const int bb = n0 >> 12;
    const int hw0 = n0 & 4095;
    const int h0 = hw0 >> 6;

    const int wm = (wid >> 2) * 16;   // warp m offset (0/16)
    const int wn = (wid & 3) * 64;    // warp n offset (0/64/128/192)

    const size_t pbase = (size_t)bb * PP + h0 * PDIM;

    // per-thread padded-row byte bases for the 8 n8 tiles (elem*2 bytes, stride 40)
    uint32_t rowb[8];
#pragma unroll
    for (int nt = 0; nt < 8; nt++) {
        int nl = wn + nt * 8 + (lane >> 2);
        int row = ((nl >> 6) + 1) * PDIM + (nl & 63) + 1;
        rowb[nt] = (uint32_t)(row * OC_BSTR + (lane & 3) * 2) * 2;
    }
    const int am = wm + (lane & 15);
    const int acol2 = (lane >> 4) << 3;

    float acc[8][4];
#pragma unroll
    for (int i = 0; i < 8; i++)
#pragma unroll
        for (int j = 0; j < 4; j++) acc[i][j] = 0.0f;

    auto load_chunk = [&](int st, int kc) {
        const uint32_t s = sbase + st * OC_STAGE;
        const int k0 = kc * 32;
        // B: 396 rows x 32ch fp16
#pragma unroll
        for (int i = 0; i < 7; i++) {
            int idx = i * 256 + tid;
            if (idx < 1584) {
                int r = idx >> 2, c4 = idx & 3;
                size_t go = (pbase + r) * 512 + k0 + c4 * 8;
                uint32_t so = (uint32_t)(r * OC_BSTR + c4 * 8) * 2;
                cp16(s + so, g_xh + go);
            }
        }
        // A: 288 rows (tap*32+m) x 32ch, hi+lo
#pragma unroll
        for (int i = 0; i < 5; i++) {
            int idx = i * 256 + tid;
            if (idx < 1152) {
                int r = idx >> 2, c4 = idx & 3;
                size_t go = (size_t)r * 512 + k0 + c4 * 8;
                uint32_t so = (uint32_t)(r * OC_ASTR + c4 * 8) * 2;
                cp16(s + OC_B_BYTES + so, g_owh + go);
                cp16(s + OC_B_BYTES + OC_A_BYTES + so, g_owl + go);
            }
        }
        CP_COMMIT();
    };

    const int stapB[9] = {(-PDIM-1)*OC_BSTR*2, (-PDIM)*OC_BSTR*2, (-PDIM+1)*OC_BSTR*2,
                          (-1)*OC_BSTR*2, 0, (1)*OC_BSTR*2,
                          (PDIM-1)*OC_BSTR*2, (PDIM)*OC_BSTR*2, (PDIM+1)*OC_BSTR*2};

    load_chunk(0, 0);

    for (int kc = 0; kc < 16; kc++) {
        const int st = kc & 1;
        if (kc + 1 < 16) { load_chunk(st ^ 1, kc + 1); CP_WAIT(1); }
        else             { CP_WAIT(0); }
        __syncthreads();

        const uint32_t sB  = sbase + st * OC_STAGE;
        const uint32_t sAh = sB + OC_B_BYTES;
        const uint32_t sAl = sAh + OC_A_BYTES;

#pragma unroll
        for (int tap = 0; tap < 9; tap++) {
            const int sb_t = stapB[tap];
#pragma unroll
            for (int ks = 0; ks < 2; ks++) {
                uint32_t ah[4], al[4];
                uint32_t ao = (uint32_t)((tap * 32 + am) * OC_ASTR + ks * 16 + acol2) * 2;
                ldsm4(ah, sAh + ao);
                ldsm4(al, sAl + ao);
#pragma unroll
                for (int nt = 0; nt < 8; nt++) {
                    uint32_t base = sB + rowb[nt] + sb_t + ks * 32;
                    uint32_t b[2];
                    b[0] = lds32(base);
                    b[1] = lds32(base + 16);
                    mma_fp(acc[nt], ah, b);
                    mma_fp(acc[nt], al, b);
                }
            }
        }
        __syncthreads();
    }

    // epilogue: write rows <27 of g_off[b][27][HW] with bias
    const int mr = wm + (lane >> 2);
    const int cb = hw0 + wn + (lane & 3) * 2;
#pragma unroll
    for (int half = 0; half < 2; half++) {
        int m = mr + half * 8;
        if (m < 27) {
            float bias = off_b[m];
            float* ob = g_off + ((size_t)(bb * 27 + m)) * HW + cb;
#pragma unroll
            for (int nt = 0; nt < 8; nt++) {
                float2 r;
                r.x = acc[nt][half * 2 + 0] + bias;
                r.y = acc[nt][half * 2 + 1] + bias;
                *(float2*)(ob + nt * 8) = r;
            }
        }
    }
}

// ---------------- deformable sampling -> fp16 im2col (mask folded) ---------
__global__ void __launch_bounds__(256)
sample_kernel(const float* __restrict__ feature)
{
    const int tid = threadIdx.x;
    const int w  = tid & 63;
    const int cg = tid >> 6;
    const int h  = blockIdx.x;
    const int k  = blockIdx.y;
    const int b  = blockIdx.z;

    const int hw = h * W + w;
    const int p  = b * HW + hw;
    const size_t obase = (size_t)(b * 27) * HW + hw;

    const float dy = g_off[obase + (size_t)k * HW];
    const float dx = g_off[obase + (size_t)(9 + k) * HW];
    const float mr = g_off[obase + (size_t)(18 + k) * HW];
    const float m  = 1.0f / (1.0f + expf(-mr));

    const int ky = k / 3 - 1, kx = k % 3 - 1;
    const float py = (float)(h + ky) + dy;
    const float px = (float)(w + kx) + dx;

    const float y0f = floorf(py), x0f = floorf(px);
    const float wy = py - y0f, wx = px - x0f;
    const int y0 = (int)y0f, x0 = (int)x0f;
    const int y1 = y0 + 1,   x1 = x0 + 1;

    const bool vy0 = (y0 >= 0) && (y0 < H);
    const bool vy1 = (y1 >= 0) && (y1 < H);
    const bool vx0 = (x0 >= 0) && (x0 < W);
    const bool vx1 = (x1 >= 0) && (x1 < W);

    float w00 = (1.0f - wy) * (1.0f - wx) * ((vy0 && vx0) ? 1.0f : 0.0f);
    float w01 = (1.0f - wy) * wx          * ((vy0 && vx1) ? 1.0f : 0.0f);
    float w10 = wy * (1.0f - wx)          * ((vy1 && vx0) ? 1.0f : 0.0f);
    float w11 = wy * wx                   * ((vy1 && vx1) ? 1.0f : 0.0f);
    w00 *= m; w01 *= m; w10 *= m; w11 *= m;

    const int yc0 = min(max(y0, 0), H - 1);
    const int yc1 = min(max(y1, 0), H - 1);
    const int xc0 = min(max(x0, 0), W - 1);
    const int xc1 = min(max(x1, 0), W - 1);

    const int a00 = yc0 * W + (63 - xc0);
    const int a01 = yc0 * W + (63 - xc1);
    const int a10 = yc1 * W + (63 - xc0);
    const int a11 = yc1 * W + (63 - xc1);

    const float* fb = feature + (size_t)b * CHW + (size_t)(cg * 64) * HW;
    size_t cidx = ((size_t)(cg * 64) * KK + k) * NPIX + p;

#pragma unroll 4
    for (int c = 0; c < 64; c++) {
        float v = w00 * fb[a00] + w01 * fb[a01] + w10 * fb[a10] + w11 * fb[a11];
        g_colh[cidx] = __float2half(v);
        fb += HW;
        cidx += (size_t)KK * NPIX;
    }
}

// ---------------- DCN GEMM: mma.sync fp16, 2-term (wh+wl)·colh -------------
#define DCN_NCH 72
#define A_STRIDE 40
#define B_STRIDE 136
#define A_BYTES (128 * A_STRIDE * 2)                 // 10240
#define B_BYTES (32 * B_STRIDE * 2)                  // 8704
#define STAGE_BYTES (2 * A_BYTES + B_BYTES)          // 29184
#define DCN_SMEM (2 * STAGE_BYTES)                   // 58368

__global__ void __launch_bounds__(256, 1)
dcn_gemm_kernel(float* __restrict__ out)
{
    extern __shared__ char smem[];
    const uint32_t sbase = smem_to_u32(smem);
    const int tid = threadIdx.x;
    const int lane = tid & 31;
    const int wid = tid >> 5;

    const int n0 = blockIdx.x * 128;
    const int m0 = blockIdx.y * 128;
    const int bb = n0 >> 12;
    const int hw0 = n0 & 4095;
    const int wm = (wid >> 2) * 64;
    const int wn = (wid & 3) * 32;

    const __half* wh = g_wh + (size_t)m0 * CK;
    const __half* wl = g_wl + (size_t)m0 * CK;

    float acc[4][4][4];
#pragma unroll
    for (int i = 0; i < 4; i++)
#pragma unroll
        for (int j = 0; j < 4; j++)
#pragma unroll
            for (int t = 0; t < 4; t++) acc[i][j][t] = 0.0f;

    auto load_chunk = [&](int st, int kt) {
        const uint32_t s = sbase + st * STAGE_BYTES;
        const int k0 = kt * 32;
#pragma unroll
        for (int i = 0; i < 2; i++) {
            int idx = i * 256 + tid;
            int r = idx >> 2, kseg = idx & 3;
            size_t go = (size_t)r * CK + k0 + kseg * 8;
            uint32_t so = (uint32_t)(r * A_STRIDE + kseg * 8) * 2;
            cp16(s + so, wh + go);
            cp16(s + A_BYTES + so, wl + go);
        }
#pragma unroll
        for (int i = 0; i < 2; i++) {
            int idx = i * 256 + tid;
            int kr = idx >> 4, nseg = idx & 15;
            size_t go = (size_t)(k0 + kr) * NPIX + n0 + nseg * 8;
            uint32_t so = (uint32_t)(kr * B_STRIDE + nseg * 8) * 2;
            cp16(s + 2 * A_BYTES + so, g_colh + go);
        }
        CP_COMMIT();
    };

    load_chunk(0, 0);

    for (int kt = 0; kt < DCN_NCH; kt++) {
        const int st = kt & 1;
        if (kt + 1 < DCN_NCH) { load_chunk(st ^ 1, kt + 1); CP_WAIT(1); }
        else                  { CP_WAIT(0); }
        __syncthreads();

        const uint32_t sAh = sbase + st * STAGE_BYTES;
        const uint32_t sAl = sAh + A_BYTES;
        const uint32_t sB  = sAh + 2 * A_BYTES;

#pragma unroll
        for (int ks = 0; ks < 2; ks++) {
            uint32_t ah[4][4], al[4][4], bf[4][2];

            const int arow = wm + (lane & 15);
            const int acol = ks * 16 + ((lane >> 4) << 3);
#pragma unroll
            for (int tm = 0; tm < 4; tm++) {
                uint32_t ao = (uint32_t)((arow + tm * 16) * A_STRIDE + acol) * 2;
                ldsm4(ah[tm], sAh + ao);
                ldsm4(al[tm], sAl + ao);
            }
            const int bkrow = ks * 16 + (lane & 15);
#pragma unroll
            for (int ng = 0; ng < 2; ng++) {
                const int bcol = wn + ng * 16 + ((lane >> 4) << 3);
                uint32_t bo = (uint32_t)(bkrow * B_STRIDE + bcol) * 2;
                uint32_t t[4];
                ldsm4t(t, sB + bo);
                bf[2*ng][0] = t[0]; bf[2*ng][1] = t[1];
                bf[2*ng+1][0] = t[2]; bf[2*ng+1][1] = t[3];
            }
#pragma unroll
            for (int tm = 0; tm < 4; tm++)
#pragma unroll
                for (int tn = 0; tn < 4; tn++) {
                    mma_fp(acc[tm][tn], ah[tm], bf[tn]);
                    mma_fp(acc[tm][tn], al[tm], bf[tn]);
                }
        }
        __syncthreads();
    }

    const int rowl = lane >> 2;
    const int colp = (lane & 3) * 2;
#pragma unroll
    for (int tm = 0; tm < 4; tm++) {
#pragma unroll
        for (int half = 0; half < 2; half++) {
            const int m = m0 + wm + tm * 16 + rowl + half * 8;
            const float add = g_add2[m];
            const float* pr = g_proj + ((size_t)bb * C + m) * HW + hw0 + wn + colp;
            float*       ob = out    + ((size_t)bb * C + m) * HW + hw0 + wn + colp;
#pragma unroll
            for (int tn = 0; tn < 4; tn++) {
                float2 p = *(const float2*)(pr + tn * 8);
                float2 r;
                r.x = fmaxf(acc[tm][tn][half * 2 + 0] + add + p.x, 0.0f);
                r.y = fmaxf(acc[tm][tn][half * 2 + 1] + add + p.y, 0.0f);
                *(float2*)(ob + tn * 8) = r;
            }
        }
    }
}

// ---------------- launch ----------------------------------------------------
extern "C" void kernel_launch(void* const* d_in, const int* in_sizes, int n_in,
                              void* d_out, int out_size)
{
    const float* feature = (const float*)d_in[0];
    const float* p1_w    = (const float*)d_in[1];
    const float* p1_b    = (const float*)d_in[2];
    const float* bn1_g   = (const float*)d_in[3];
    const float* bn1_b   = (const float*)d_in[4];
    const float* bn1_m   = (const float*)d_in[5];
    const float* bn1_v   = (const float*)d_in[6];
    const float* off_w   = (const float*)d_in[7];
    const float* off_b   = (const float*)d_in[8];
    const float* dcn_w   = (const float*)d_in[9];
    const float* dcn_b   = (const float*)d_in[10];
    const float* bn2_g   = (const float*)d_in[11];
    const float* bn2_b   = (const float*)d_in[12];
    const float* bn2_m   = (const float*)d_in[13];
    const float* bn2_v   = (const float*)d_in[14];

    cudaFuncSetAttribute(dcn_gemm_kernel,
                         cudaFuncAttributeMaxDynamicSharedMemorySize, DCN_SMEM);
    cudaFuncSetAttribute(off_gemm_kernel,
                         cudaFuncAttributeMaxDynamicSharedMemorySize, OC_SMEM);

    prep_kernel<<<1, 256>>>(p1_b, bn1_g, bn1_b, bn1_m, bn1_v,
                            dcn_b, bn2_g, bn2_b, bn2_m, bn2_v);
    split_w_kernel<<<(C * CK + 255) / 256, 256>>>(dcn_w);
    prep_offw_kernel<<<(9 * 32 * 512 + 255) / 256, 256>>>(off_w);
    zero_pad_kernel<<<(BATCH * 260 * 512 + 255) / 256, 256>>>();

    proj_gemm_kernel<<<dim3(NPIX / BN, C / BM), 256>>>(p1_w, feature);

    pack_kernel<<<dim3(2, 16, 512), dim3(32, 8)>>>(feature);

    off_gemm_kernel<<<NPIX / 256, 256, OC_SMEM>>>(off_b);

    sample_kernel<<<dim3(H, KK, BATCH), 256>>>(feature);

    dcn_gemm_kernel<<<dim3(NPIX / 128, C / 128), 256, DCN_SMEM>>>((float*)d_out);
}

// round 7
// speedup vs baseline: 3.3164x; 1.1007x over previous
#include <cuda_runtime.h>
#include <cuda_bf16.h>
#include <cuda_fp16.h>
#include <math.h>
#include <stdint.h>

// Problem constants
#define BATCH 8
#define C 256
#define H 64
#define W 64
#define HW 4096
#define NPIX 32768
#define KK 9
#define CK 2304
#define CHW (C*HW)
#define PDIM 66
#define PP (PDIM*PDIM)     // 4356 padded positions per batch

// ---------------- scratch (device globals; no allocation) ----------------
__device__ float g_proj[(size_t)BATCH * CHW];                    // 33.5 MB
__device__ float g_off[(size_t)BATCH * 27 * HW];                 // 3.5 MB
__device__ __half g_colh[(size_t)CK * NPIX];                     // 151 MB (fp16, mask folded)
__device__ __half g_wh[(size_t)C * CK];                          // dcn weights hi (scaled by inv2)
__device__ __half g_wl[(size_t)C * CK];                          // dcn weights lo
__device__ __half g_xh[(size_t)BATCH * PP * 512];                // X^T padded (fp16 single)
__device__ __half g_owh[(size_t)9 * 32 * 512];                   // offset weights hi (fp16)
__device__ __half g_owl[(size_t)9 * 32 * 512];                   // offset weights lo
__device__ __half g_fh[(size_t)BATCH * CHW];                     // feature fp16 hi (16.8 MB)
__device__ __half g_fl[(size_t)BATCH * CHW];                     // feature fp16 lo
__device__ __half g_w1h[(size_t)C * C];                          // p1_w*inv1 hi
__device__ __half g_w1l[(size_t)C * C];                          // p1_w*inv1 lo
__device__ float g_inv1[C], g_add1[C], g_inv2[C], g_add2[C];

// ================= mma.sync / ldmatrix / cp.async helpers =================
__device__ __forceinline__ uint32_t smem_to_u32(const void* p) {
    uint32_t a;
    asm("{ .reg .u64 t; cvta.to.shared.u64 t, %1; cvt.u32.u64 %0, t; }" : "=r"(a) : "l"(p));
    return a;
}
__device__ __forceinline__ void cp16(uint32_t s, const void* g) {
    asm volatile("cp.async.cg.shared.global [%0], [%1], 16;" :: "r"(s), "l"(g));
}
#define CP_COMMIT() asm volatile("cp.async.commit_group;" ::: "memory")
#define CP_WAIT(n)  asm volatile("cp.async.wait_group %0;" :: "n"(n) : "memory")

__device__ __forceinline__ void ldsm4(uint32_t* r, uint32_t addr) {
    asm volatile("ldmatrix.sync.aligned.m8n8.x4.shared.b16 {%0,%1,%2,%3}, [%4];"
        : "=r"(r[0]), "=r"(r[1]), "=r"(r[2]), "=r"(r[3]) : "r"(addr));
}
__device__ __forceinline__ void ldsm4t(uint32_t* r, uint32_t addr) {
    asm volatile("ldmatrix.sync.aligned.m8n8.x4.trans.shared.b16 {%0,%1,%2,%3}, [%4];"
        : "=r"(r[0]), "=r"(r[1]), "=r"(r[2]), "=r"(r[3]) : "r"(addr));
}
__device__ __forceinline__ uint32_t lds32(uint32_t addr) {
    uint32_t v;
    asm volatile("ld.shared.b32 %0, [%1];" : "=r"(v) : "r"(addr));
    return v;
}
// fp16 MMA
__device__ __forceinline__ void mma_fp(float* c, const uint32_t* a, const uint32_t* b) {
    asm volatile("mma.sync.aligned.m16n8k16.row.col.f32.f16.f16.f32 "
        "{%0,%1,%2,%3}, {%4,%5,%6,%7}, {%8,%9}, {%0,%1,%2,%3};"
        : "+f"(c[0]), "+f"(c[1]), "+f"(c[2]), "+f"(c[3])
        : "r"(a[0]), "r"(a[1]), "r"(a[2]), "r"(a[3]), "r"(b[0]), "r"(b[1]));
}

// ---------------- prep -----------------------------------------------------
__global__ void prep_kernel(const float* __restrict__ p1_b,
                            const float* __restrict__ bn1_g, const float* __restrict__ bn1_b,
                            const float* __restrict__ bn1_m, const float* __restrict__ bn1_v,
                            const float* __restrict__ dcn_b,
                            const float* __restrict__ bn2_g, const float* __restrict__ bn2_b,
                            const float* __restrict__ bn2_m, const float* __restrict__ bn2_v)
{
    int o = threadIdx.x;
    if (o < C) {
        float inv1 = bn1_g[o] / sqrtf(bn1_v[o] + 1e-5f);
        g_inv1[o] = inv1;
        g_add1[o] = bn1_b[o] - bn1_m[o] * inv1 + p1_b[o] * inv1;
        float inv2 = bn2_g[o] / sqrtf(bn2_v[o] + 1e-5f);
        g_inv2[o] = inv2;
        g_add2[o] = bn2_b[o] - bn2_m[o] * inv2 + dcn_b[o] * inv2;
    }
}

// split dcn weights (scaled by inv2) into fp16 hi/lo
__global__ void split_w_kernel(const float* __restrict__ dcn_w)
{
    int idx = blockIdx.x * 256 + threadIdx.x;
    if (idx < C * CK) {
        int o = idx / CK;
        float v = dcn_w[idx] * g_inv2[o];
        __half hi = __float2half(v);
        float lo = v - __half2float(hi);
        g_wh[idx] = hi;
        g_wl[idx] = __float2half(lo);
    }
}

// split p1 weights (scaled by inv1) into fp16 hi/lo
__global__ void split_w1_kernel(const float* __restrict__ p1_w)
{
    int idx = blockIdx.x * 256 + threadIdx.x;
    if (idx < C * C) {
        int o = idx >> 8;
        float v = p1_w[idx] * g_inv1[o];
        __half hi = __float2half(v);
        g_w1h[idx] = hi;
        g_w1l[idx] = __float2half(v - __half2float(hi));
    }
}

// feature -> fp16 hi/lo
__global__ void conv_f16_kernel(const float* __restrict__ feature)
{
    size_t idx = (size_t)blockIdx.x * 256 + threadIdx.x;
    if (idx < (size_t)BATCH * CHW) {
        float v = feature[idx];
        __half hi = __float2half(v);
        g_fh[idx] = hi;
        g_fl[idx] = __float2half(v - __half2float(hi));
    }
}

// repack offset weights: off_w[27][512][3][3] -> g_owh/l [tap(9)][32][512] fp16 hi/lo
__global__ void prep_offw_kernel(const float* __restrict__ off_w)
{
    int idx = blockIdx.x * 256 + threadIdx.x;
    if (idx < 9 * 32 * 512) {
        int t = idx >> 14;            // tap
        int r = (idx >> 9) & 31;      // output row (27 used)
        int c = idx & 511;            // input channel
        float v = 0.0f;
        if (r < 27) {
            int kh = t / 3, kw = t % 3;
            v = off_w[((size_t)(r * 512 + c) * 3 + kh) * 3 + kw];
        }
        __half hi = __float2half(v);
        g_owh[idx] = hi;
        g_owl[idx] = __float2half(v - __half2float(hi));
    }
}

// zero the padding ring of g_xh
__global__ void zero_pad_kernel()
{
    int idx = blockIdx.x * 256 + threadIdx.x;
    if (idx < BATCH * 260 * 512) {
        int c = idx & 511;
        int rest = idx >> 9;
        int pos = rest % 260;
        int b = rest / 260;
        int yp, xp;
        if (pos < 66)       { yp = 0;  xp = pos; }
        else if (pos < 132) { yp = 65; xp = pos - 66; }
        else {
            int i = pos - 132;
            yp = 1 + (i >> 1);
            xp = (i & 1) * 65;
        }
        size_t a = ((size_t)b * PP + yp * PDIM + xp) * 512 + c;
        g_xh[a] = __float2half(0.0f);
    }
}

// pack concat(flip(feature), proj) transposed -> X^T[b][pad pos][512] fp16
__global__ void __launch_bounds__(256)
pack_kernel(const float* __restrict__ feature)
{
    __shared__ float tile[32][33];
    const int tx = threadIdx.x, ty = threadIdx.y;
    const int b = blockIdx.z >> 6;
    const int y = blockIdx.z & 63;
    const int x0 = blockIdx.x * 32;
    const int c0 = blockIdx.y * 32;

#pragma unroll
    for (int j = 0; j < 4; j++) {
        int c = c0 + ty + j * 8;
        int x = x0 + tx;
        float v;
        if (c < 256) v = feature[((size_t)(b * 256 + c) * 64 + y) * 64 + (63 - x)];
        else         v = g_proj[((size_t)(b * 256 + (c - 256)) * 64 + y) * 64 + x];
        tile[ty + j * 8][tx] = v;
    }
    __syncthreads();
#pragma unroll
    for (int j = 0; j < 4; j++) {
        int xl = ty + j * 8;
        float v = tile[tx][xl];
        size_t a = ((size_t)b * PP + (y + 1) * PDIM + (x0 + xl + 1)) * 512 + c0 + tx;
        g_xh[a] = __float2half(v);
    }
}

// ---------------- proj GEMM: mma.sync fp16 3-term --------------------------
// D[m][pix] = sum_c W1[m][c]*F[c][pix];  A = g_w1h/l [256][256], B = g_fh/l.
#define PJ_NCH 8
#define PJ_ASTR 40
#define PJ_BSTR 136
#define PJ_A_BYTES (128 * PJ_ASTR * 2)               // 10240
#define PJ_B_BYTES (32 * PJ_BSTR * 2)                // 8704
#define PJ_STAGE (2 * PJ_A_BYTES + 2 * PJ_B_BYTES)   // 37888
#define PJ_SMEM (2 * PJ_STAGE)                       // 75776

__global__ void __launch_bounds__(256, 1)
proj_tc_kernel()
{
    extern __shared__ char smem[];
    const uint32_t sbase = smem_to_u32(smem);
    const int tid = threadIdx.x;
    const int lane = tid & 31;
    const int wid = tid >> 5;

    const int n0 = blockIdx.x * 128;
    const int m0 = blockIdx.y * 128;
    const int bb = n0 >> 12;
    const int hw0 = n0 & 4095;
    const int wm = (wid >> 2) * 64;
    const int wn = (wid & 3) * 32;

    const __half* wh = g_w1h + (size_t)m0 * C;
    const __half* wl = g_w1l + (size_t)m0 * C;
    const __half* fh = g_fh + (size_t)bb * CHW + hw0;
    const __half* fl = g_fl + (size_t)bb * CHW + hw0;

    float acc[4][4][4];
#pragma unroll
    for (int i = 0; i < 4; i++)
#pragma unroll
        for (int j = 0; j < 4; j++)
#pragma unroll
            for (int t = 0; t < 4; t++) acc[i][j][t] = 0.0f;

    auto load_chunk = [&](int st, int kt) {
        const uint32_t s = sbase + st * PJ_STAGE;
        const int k0 = kt * 32;
#pragma unroll
        for (int i = 0; i < 2; i++) {
            int idx = i * 256 + tid;
            int r = idx >> 2, kseg = idx & 3;
            size_t go = (size_t)r * C + k0 + kseg * 8;
            uint32_t so = (uint32_t)(r * PJ_ASTR + kseg * 8) * 2;
            cp16(s + so, wh + go);
            cp16(s + PJ_A_BYTES + so, wl + go);
        }
#pragma unroll
        for (int i = 0; i < 2; i++) {
            int idx = i * 256 + tid;
            int kr = idx >> 4, nseg = idx & 15;
            size_t go = (size_t)(k0 + kr) * HW + nseg * 8;
            uint32_t so = (uint32_t)(kr * PJ_BSTR + nseg * 8) * 2;
            cp16(s + 2 * PJ_A_BYTES + so, fh + go);
            cp16(s + 2 * PJ_A_BYTES + PJ_B_BYTES + so, fl + go);
        }
        CP_COMMIT();
    };

    load_chunk(0, 0);

    for (int kt = 0; kt < PJ_NCH; kt++) {
        const int st = kt & 1;
        if (kt + 1 < PJ_NCH) { load_chunk(st ^ 1, kt + 1); CP_WAIT(1); }
        else                 { CP_WAIT(0); }
        __syncthreads();

        const uint32_t sAh = sbase + st * PJ_STAGE;
        const uint32_t sAl = sAh + PJ_A_BYTES;
        const uint32_t sBh = sAh + 2 * PJ_A_BYTES;
        const uint32_t sBl = sBh + PJ_B_BYTES;

#pragma unroll
        for (int ks = 0; ks < 2; ks++) {
            uint32_t ah[4][4], al[4][4], bh[4][2], bl[4][2];

            const int arow = wm + (lane & 15);
            const int acol = ks * 16 + ((lane >> 4) << 3);
#pragma unroll
            for (int tm = 0; tm < 4; tm++) {
                uint32_t ao = (uint32_t)((arow + tm * 16) * PJ_ASTR + acol) * 2;
                ldsm4(ah[tm], sAh + ao);
                ldsm4(al[tm], sAl + ao);
            }
            const int bkrow = ks * 16 + (lane & 15);
#pragma unroll
            for (int ng = 0; ng < 2; ng++) {
                const int bcol = wn + ng * 16 + ((lane >> 4) << 3);
                uint32_t bo = (uint32_t)(bkrow * PJ_BSTR + bcol) * 2;
                uint32_t t[4];
                ldsm4t(t, sBh + bo);
                bh[2*ng][0] = t[0]; bh[2*ng][1] = t[1];
                bh[2*ng+1][0] = t[2]; bh[2*ng+1][1] = t[3];
                ldsm4t(t, sBl + bo);
                bl[2*ng][0] = t[0]; bl[2*ng][1] = t[1];
                bl[2*ng+1][0] = t[2]; bl[2*ng+1][1] = t[3];
            }
#pragma unroll
            for (int tm = 0; tm < 4; tm++)
#pragma unroll
                for (int tn = 0; tn < 4; tn++) {
                    mma_fp(acc[tm][tn], ah[tm], bh[tn]);
                    mma_fp(acc[tm][tn], ah[tm], bl[tn]);
                    mma_fp(acc[tm][tn], al[tm], bh[tn]);
                }
        }
        __syncthreads();
    }

    const int rowl = lane >> 2;
    const int colp = (lane & 3) * 2;
#pragma unroll
    for (int tm = 0; tm < 4; tm++) {
#pragma unroll
        for (int half = 0; half < 2; half++) {
            const int m = m0 + wm + tm * 16 + rowl + half * 8;
            const float add = g_add1[m];
            float* ob = g_proj + ((size_t)bb * C + m) * HW + hw0 + wn + colp;
#pragma unroll
            for (int tn = 0; tn < 4; tn++) {
                float2 r;
                r.x = acc[tm][tn][half * 2 + 0] + add;
                r.y = acc[tm][tn][half * 2 + 1] + add;
                *(float2*)(ob + tn * 8) = r;
            }
        }
    }
}

// ---------------- offset conv as tensor-core GEMM (fp16 2-term) ------------
#define OC_ROWS 396
#define OC_BSTR 40
#define OC_ASTR 40
#define OC_B_BYTES (OC_ROWS * OC_BSTR * 2)         // 31680
#define OC_A_BYTES (9 * 32 * OC_ASTR * 2)          // 23040 per component
#define OC_STAGE (OC_B_BYTES + 2 * OC_A_BYTES)     // 77760
#define OC_SMEM (2 * OC_STAGE)                     // 155520

__global__ void __launch_bounds__(256, 1)
off_gemm_kernel(const float* __restrict__ off_b)
{
    extern __shared__ char smem[];
    const uint32_t sbase = smem_to_u32(smem);
    const int tid = threadIdx.x;
    const int lane = tid & 31;
    const int wid = tid >> 5;

    const int n0 = blockIdx.x * 256;
    const int bb = n0 >> 12;
    const int hw0 = n0 & 4095;
    const int h0 = hw0 >> 6;

    const int wm = (wid >> 2) * 16;   // warp m offset (0/16)
    const int wn = (wid & 3) * 64;    // warp n offset (0/64/128/192)

    const size_t pbase = (size_t)bb * PP + h0 * PDIM;

    uint32_t rowb[8];
#pragma unroll
    for (int nt = 0; nt < 8; nt++) {
        int nl = wn + nt * 8 + (lane >> 2);
        int row = ((nl >> 6) + 1) * PDIM + (nl & 63) + 1;
        rowb[nt] = (uint32_t)(row * OC_BSTR + (lane & 3) * 2) * 2;
    }
    const int am = wm + (lane & 15);
    const int acol2 = (lane >> 4) << 3;

    float acc[8][4];
#pragma unroll
    for (int i = 0; i < 8; i++)
#pragma unroll
        for (int j = 0; j < 4; j++) acc[i][j] = 0.0f;

    auto load_chunk = [&](int st, int kc) {
        const uint32_t s = sbase + st * OC_STAGE;
        const int k0 = kc * 32;
#pragma unroll
        for (int i = 0; i < 7; i++) {
            int idx = i * 256 + tid;
            if (idx < 1584) {
                int r = idx >> 2, c4 = idx & 3;
                size_t go = (pbase + r) * 512 + k0 + c4 * 8;
                uint32_t so = (uint32_t)(r * OC_BSTR + c4 * 8) * 2;
                cp16(s + so, g_xh + go);
            }
        }
#pragma unroll
        for (int i = 0; i < 5; i++) {
            int idx = i * 256 + tid;
            if (idx < 1152) {
                int r = idx >> 2, c4 = idx & 3;
                size_t go = (size_t)r * 512 + k0 + c4 * 8;
                uint32_t so = (uint32_t)(r * OC_ASTR + c4 * 8) * 2;
                cp16(s + OC_B_BYTES + so, g_owh + go);
                cp16(s + OC_B_BYTES + OC_A_BYTES + so, g_owl + go);
            }
        }
        CP_COMMIT();
    };

    const int stapB[9] = {(-PDIM-1)*OC_BSTR*2, (-PDIM)*OC_BSTR*2, (-PDIM+1)*OC_BSTR*2,
                          (-1)*OC_BSTR*2, 0, (1)*OC_BSTR*2,
                          (PDIM-1)*OC_BSTR*2, (PDIM)*OC_BSTR*2, (PDIM+1)*OC_BSTR*2};

    load_chunk(0, 0);

    for (int kc = 0; kc < 16; kc++) {
        const int st = kc & 1;
        if (kc + 1 < 16) { load_chunk(st ^ 1, kc + 1); CP_WAIT(1); }
        else             { CP_WAIT(0); }
        __syncthreads();

        const uint32_t sB  = sbase + st * OC_STAGE;
        const uint32_t sAh = sB + OC_B_BYTES;
        const uint32_t sAl = sAh + OC_A_BYTES;

#pragma unroll
        for (int tap = 0; tap < 9; tap++) {
            const int sb_t = stapB[tap];
#pragma unroll
            for (int ks = 0; ks < 2; ks++) {
                uint32_t ah[4], al[4];
                uint32_t ao = (uint32_t)((tap * 32 + am) * OC_ASTR + ks * 16 + acol2) * 2;
                ldsm4(ah, sAh + ao);
                ldsm4(al, sAl + ao);
#pragma unroll
                for (int nt = 0; nt < 8; nt++) {
                    uint32_t base = sB + rowb[nt] + sb_t + ks * 32;
                    uint32_t b[2];
                    b[0] = lds32(base);
                    b[1] = lds32(base + 16);
                    mma_fp(acc[nt], ah, b);
                    mma_fp(acc[nt], al, b);
                }
            }
        }
        __syncthreads();
    }

    const int mr = wm + (lane >> 2);
    const int cb = hw0 + wn + (lane & 3) * 2;
#pragma unroll
    for (int half = 0; half < 2; half++) {
        int m = mr + half * 8;
        if (m < 27) {
            float bias = off_b[m];
            float* ob = g_off + ((size_t)(bb * 27 + m)) * HW + cb;
#pragma unroll
            for (int nt = 0; nt < 8; nt++) {
                float2 r;
                r.x = acc[nt][half * 2 + 0] + bias;
                r.y = acc[nt][half * 2 + 1] + bias;
                *(float2*)(ob + nt * 8) = r;
            }
        }
    }
}

// ---------------- deformable sampling -> fp16 im2col (mask folded) ---------
__global__ void __launch_bounds__(256)
sample_kernel(const float* __restrict__ feature)
{
    const int tid = threadIdx.x;
    const int w  = tid & 63;
    const int cg = tid >> 6;
    const int h  = blockIdx.x;
    const int k  = blockIdx.y;
    const int b  = blockIdx.z;

    const int hw = h * W + w;
    const int p  = b * HW + hw;
    const size_t obase = (size_t)(b * 27) * HW + hw;

    const float dy = g_off[obase + (size_t)k * HW];
    const float dx = g_off[obase + (size_t)(9 + k) * HW];
    const float mr = g_off[obase + (size_t)(18 + k) * HW];
    const float m  = 1.0f / (1.0f + expf(-mr));

    const int ky = k / 3 - 1, kx = k % 3 - 1;
    const float py = (float)(h + ky) + dy;
    const float px = (float)(w + kx) + dx;

    const float y0f = floorf(py), x0f = floorf(px);
    const float wy = py - y0f, wx = px - x0f;
    const int y0 = (int)y0f, x0 = (int)x0f;
    const int y1 = y0 + 1,   x1 = x0 + 1;

    const bool vy0 = (y0 >= 0) && (y0 < H);
    const bool vy1 = (y1 >= 0) && (y1 < H);
    const bool vx0 = (x0 >= 0) && (x0 < W);
    const bool vx1 = (x1 >= 0) && (x1 < W);

    float w00 = (1.0f - wy) * (1.0f - wx) * ((vy0 && vx0) ? 1.0f : 0.0f);
    float w01 = (1.0f - wy) * wx          * ((vy0 && vx1) ? 1.0f : 0.0f);
    float w10 = wy * (1.0f - wx)          * ((vy1 && vx0) ? 1.0f : 0.0f);
    float w11 = wy * wx                   * ((vy1 && vx1) ? 1.0f : 0.0f);
    w00 *= m; w01 *= m; w10 *= m; w11 *= m;

    const int yc0 = min(max(y0, 0), H - 1);
    const int yc1 = min(max(y1, 0), H - 1);
    const int xc0 = min(max(x0, 0), W - 1);
    const int xc1 = min(max(x1, 0), W - 1);

    const int a00 = yc0 * W + (63 - xc0);
    const int a01 = yc0 * W + (63 - xc1);
    const int a10 = yc1 * W + (63 - xc0);
    const int a11 = yc1 * W + (63 - xc1);

    const float* fb = feature + (size_t)b * CHW + (size_t)(cg * 64) * HW;
    size_t cidx = ((size_t)(cg * 64) * KK + k) * NPIX + p;

#pragma unroll 4
    for (int c = 0; c < 64; c++) {
        float v = w00 * fb[a00] + w01 * fb[a01] + w10 * fb[a10] + w11 * fb[a11];
        g_colh[cidx] = __float2half(v);
        fb += HW;
        cidx += (size_t)KK * NPIX;
    }
}

// ---------------- DCN GEMM: mma.sync fp16, 2-term (wh+wl)·colh -------------
#define DCN_NCH 72
#define A_STRIDE 40
#define B_STRIDE 136
#define A_BYTES (128 * A_STRIDE * 2)                 // 10240
#define B_BYTES (32 * B_STRIDE * 2)                  // 8704
#define STAGE_BYTES (2 * A_BYTES + B_BYTES)          // 29184
#define DCN_SMEM (2 * STAGE_BYTES)                   // 58368

__global__ void __launch_bounds__(256, 1)
dcn_gemm_kernel(float* __restrict__ out)
{
    extern __shared__ char smem[];
    const uint32_t sbase = smem_to_u32(smem);
    const int tid = threadIdx.x;
    const int lane = tid & 31;
    const int wid = tid >> 5;

    const int n0 = blockIdx.x * 128;
    const int m0 = blockIdx.y * 128;
    const int bb = n0 >> 12;
    const int hw0 = n0 & 4095;
    const int wm = (wid >> 2) * 64;
    const int wn = (wid & 3) * 32;

    const __half* wh = g_wh + (size_t)m0 * CK;
    const __half* wl = g_wl + (size_t)m0 * CK;

    float acc[4][4][4];
#pragma unroll
    for (int i = 0; i < 4; i++)
#pragma unroll
        for (int j = 0; j < 4; j++)
#pragma unroll
            for (int t = 0; t < 4; t++) acc[i][j][t] = 0.0f;

    auto load_chunk = [&](int st, int kt) {
        const uint32_t s = sbase + st * STAGE_BYTES;
        const int k0 = kt * 32;
#pragma unroll
        for (int i = 0; i < 2; i++) {
            int idx = i * 256 + tid;
            int r = idx >> 2, kseg = idx & 3;
            size_t go = (size_t)r * CK + k0 + kseg * 8;
            uint32_t so = (uint32_t)(r * A_STRIDE + kseg * 8) * 2;
            cp16(s + so, wh + go);
            cp16(s + A_BYTES + so, wl + go);
        }
#pragma unroll
        for (int i = 0; i < 2; i++) {
            int idx = i * 256 + tid;
            int kr = idx >> 4, nseg = idx & 15;
            size_t go = (size_t)(k0 + kr) * NPIX + n0 + nseg * 8;
            uint32_t so = (uint32_t)(kr * B_STRIDE + nseg * 8) * 2;
            cp16(s + 2 * A_BYTES + so, g_colh + go);
        }
        CP_COMMIT();
    };

    load_chunk(0, 0);

    for (int kt = 0; kt < DCN_NCH; kt++) {
        const int st = kt & 1;
        if (kt + 1 < DCN_NCH) { load_chunk(st ^ 1, kt + 1); CP_WAIT(1); }
        else                  { CP_WAIT(0); }
        __syncthreads();

        const uint32_t sAh = sbase + st * STAGE_BYTES;
        const uint32_t sAl = sAh + A_BYTES;
        const uint32_t sB  = sAh + 2 * A_BYTES;

#pragma unroll
        for (int ks = 0; ks < 2; ks++) {
            uint32_t ah[4][4], al[4][4], bf[4][2];

            const int arow = wm + (lane & 15);
            const int acol = ks * 16 + ((lane >> 4) << 3);
#pragma unroll
            for (int tm = 0; tm < 4; tm++) {
                uint32_t ao = (uint32_t)((arow + tm * 16) * A_STRIDE + acol) * 2;
                ldsm4(ah[tm], sAh + ao);
                ldsm4(al[tm], sAl + ao);
            }
            const int bkrow = ks * 16 + (lane & 15);
#pragma unroll
            for (int ng = 0; ng < 2; ng++) {
                const int bcol = wn + ng * 16 + ((lane >> 4) << 3);
                uint32_t bo = (uint32_t)(bkrow * B_STRIDE + bcol) * 2;
                uint32_t t[4];
                ldsm4t(t, sB + bo);
                bf[2*ng][0] = t[0]; bf[2*ng][1] = t[1];
                bf[2*ng+1][0] = t[2]; bf[2*ng+1][1] = t[3];
            }
#pragma unroll
            for (int tm = 0; tm < 4; tm++)
#pragma unroll
                for (int tn = 0; tn < 4; tn++) {
                    mma_fp(acc[tm][tn], ah[tm], bf[tn]);
                    mma_fp(acc[tm][tn], al[tm], bf[tn]);
                }
        }
        __syncthreads();
    }

    const int rowl = lane >> 2;
    const int colp = (lane & 3) * 2;
#pragma unroll
    for (int tm = 0; tm < 4; tm++) {
#pragma unroll
        for (int half = 0; half < 2; half++) {
            const int m = m0 + wm + tm * 16 + rowl + half * 8;
            const float add = g_add2[m];
            const float* pr = g_proj + ((size_t)bb * C + m) * HW + hw0 + wn + colp;
            float*       ob = out    + ((size_t)bb * C + m) * HW + hw0 + wn + colp;
#pragma unroll
            for (int tn = 0; tn < 4; tn++) {
                float2 p = *(const float2*)(pr + tn * 8);
                float2 r;
                r.x = fmaxf(acc[tm][tn][half * 2 + 0] + add + p.x, 0.0f);
                r.y = fmaxf(acc[tm][tn][half * 2 + 1] + add + p.y, 0.0f);
                *(float2*)(ob + tn * 8) = r;
            }
        }
    }
}

// ---------------- launch ----------------------------------------------------
extern "C" void kernel_launch(void* const* d_in, const int* in_sizes, int n_in,
                              void* d_out, int out_size)
{
    const float* feature = (const float*)d_in[0];
    const float* p1_w    = (const float*)d_in[1];
    const float* p1_b    = (const float*)d_in[2];
    const float* bn1_g   = (const float*)d_in[3];
    const float* bn1_b   = (const float*)d_in[4];
    const float* bn1_m   = (const float*)d_in[5];
    const float* bn1_v   = (const float*)d_in[6];
    const float* off_w   = (const float*)d_in[7];
    const float* off_b   = (const float*)d_in[8];
    const float* dcn_w   = (const float*)d_in[9];
    const float* dcn_b   = (const float*)d_in[10];
    const float* bn2_g   = (const float*)d_in[11];
    const float* bn2_b   = (const float*)d_in[12];
    const float* bn2_m   = (const float*)d_in[13];
    const float* bn2_v   = (const float*)d_in[14];

    cudaFuncSetAttribute(dcn_gemm_kernel,
                         cudaFuncAttributeMaxDynamicSharedMemorySize, DCN_SMEM);
    cudaFuncSetAttribute(off_gemm_kernel,
                         cudaFuncAttributeMaxDynamicSharedMemorySize, OC_SMEM);
    cudaFuncSetAttribute(proj_tc_kernel,
                         cudaFuncAttributeMaxDynamicSharedMemorySize, PJ_SMEM);

    prep_kernel<<<1, 256>>>(p1_b, bn1_g, bn1_b, bn1_m, bn1_v,
                            dcn_b, bn2_g, bn2_b, bn2_m, bn2_v);
    split_w_kernel<<<(C * CK + 255) / 256, 256>>>(dcn_w);
    split_w1_kernel<<<(C * C + 255) / 256, 256>>>(p1_w);
    conv_f16_kernel<<<(int)(((size_t)BATCH * CHW + 255) / 256), 256>>>(feature);
    prep_offw_kernel<<<(9 * 32 * 512 + 255) / 256, 256>>>(off_w);
    zero_pad_kernel<<<(BATCH * 260 * 512 + 255) / 256, 256>>>();

    proj_tc_kernel<<<dim3(NPIX / 128, 2), 256, PJ_SMEM>>>();

    pack_kernel<<<dim3(2, 16, 512), dim3(32, 8)>>>(feature);

    off_gemm_kernel<<<NPIX / 256, 256, OC_SMEM>>>(off_b);

    sample_kernel<<<dim3(H, KK, BATCH), 256>>>(feature);

    dcn_gemm_kernel<<<dim3(NPIX / 128, C / 128), 256, DCN_SMEM>>>((float*)d_out);
}

// round 8
// speedup vs baseline: 4.2647x; 1.2859x over previous
#include <cuda_runtime.h>
#include <cuda_bf16.h>
#include <cuda_fp16.h>
#include <math.h>
#include <stdint.h>

// Problem constants
#define BATCH 8
#define C 256
#define H 64
#define W 64
#define HW 4096
#define NPIX 32768
#define KK 9
#define CK 2304
#define CHW (C*HW)
#define PDIM 66
#define PP (PDIM*PDIM)     // 4356 padded positions per batch

// ---------------- scratch (device globals; no allocation) ----------------
__device__ float g_proj[(size_t)BATCH * CHW];                    // 33.5 MB
__device__ float g_off[(size_t)BATCH * 27 * HW];                 // 3.5 MB
__device__ __half g_colh[(size_t)CK * NPIX];                     // 151 MB (fp16, mask folded)
__device__ __half g_wh[(size_t)C * CK];                          // dcn weights fp16 (scaled by inv2)
__device__ __half g_xh[(size_t)BATCH * PP * 512];                // X^T padded (fp16)
__device__ __half g_owh[(size_t)9 * 32 * 512];                   // offset weights fp16
__device__ __half g_fh[(size_t)BATCH * CHW];                     // feature fp16 hi
__device__ __half g_fl[(size_t)BATCH * CHW];                     // feature fp16 lo
__device__ __half g_w1h[(size_t)C * C];                          // p1_w*inv1 hi
__device__ __half g_w1l[(size_t)C * C];                          // p1_w*inv1 lo
__device__ float g_inv1[C], g_add1[C], g_inv2[C], g_add2[C];

// ================= mma.sync / ldmatrix / cp.async helpers =================
__device__ __forceinline__ uint32_t smem_to_u32(const void* p) {
    uint32_t a;
    asm("{ .reg .u64 t; cvta.to.shared.u64 t, %1; cvt.u32.u64 %0, t; }" : "=r"(a) : "l"(p));
    return a;
}
__device__ __forceinline__ void cp16(uint32_t s, const void* g) {
    asm volatile("cp.async.cg.shared.global [%0], [%1], 16;" :: "r"(s), "l"(g));
}
#define CP_COMMIT() asm volatile("cp.async.commit_group;" ::: "memory")
#define CP_WAIT(n)  asm volatile("cp.async.wait_group %0;" :: "n"(n) : "memory")

__device__ __forceinline__ void ldsm4(uint32_t* r, uint32_t addr) {
    asm volatile("ldmatrix.sync.aligned.m8n8.x4.shared.b16 {%0,%1,%2,%3}, [%4];"
        : "=r"(r[0]), "=r"(r[1]), "=r"(r[2]), "=r"(r[3]) : "r"(addr));
}
__device__ __forceinline__ void ldsm4t(uint32_t* r, uint32_t addr) {
    asm volatile("ldmatrix.sync.aligned.m8n8.x4.trans.shared.b16 {%0,%1,%2,%3}, [%4];"
        : "=r"(r[0]), "=r"(r[1]), "=r"(r[2]), "=r"(r[3]) : "r"(addr));
}
__device__ __forceinline__ uint32_t lds32(uint32_t addr) {
    uint32_t v;
    asm volatile("ld.shared.b32 %0, [%1];" : "=r"(v) : "r"(addr));
    return v;
}
__device__ __forceinline__ void mma_fp(float* c, const uint32_t* a, const uint32_t* b) {
    asm volatile("mma.sync.aligned.m16n8k16.row.col.f32.f16.f16.f32 "
        "{%0,%1,%2,%3}, {%4,%5,%6,%7}, {%8,%9}, {%0,%1,%2,%3};"
        : "+f"(c[0]), "+f"(c[1]), "+f"(c[2]), "+f"(c[3])
        : "r"(a[0]), "r"(a[1]), "r"(a[2]), "r"(a[3]), "r"(b[0]), "r"(b[1]));
}

// ---------------- prep -----------------------------------------------------
__global__ void prep_kernel(const float* __restrict__ p1_b,
                            const float* __restrict__ bn1_g, const float* __restrict__ bn1_b,
                            const float* __restrict__ bn1_m, const float* __restrict__ bn1_v,
                            const float* __restrict__ dcn_b,
                            const float* __restrict__ bn2_g, const float* __restrict__ bn2_b,
                            const float* __restrict__ bn2_m, const float* __restrict__ bn2_v)
{
    int o = threadIdx.x;
    if (o < C) {
        float inv1 = bn1_g[o] / sqrtf(bn1_v[o] + 1e-5f);
        g_inv1[o] = inv1;
        g_add1[o] = bn1_b[o] - bn1_m[o] * inv1 + p1_b[o] * inv1;
        float inv2 = bn2_g[o] / sqrtf(bn2_v[o] + 1e-5f);
        g_inv2[o] = inv2;
        g_add2[o] = bn2_b[o] - bn2_m[o] * inv2 + dcn_b[o] * inv2;
    }
}

// dcn weights (scaled by inv2) -> fp16
__global__ void split_w_kernel(const float* __restrict__ dcn_w)
{
    int idx = blockIdx.x * 256 + threadIdx.x;
    if (idx < C * CK) {
        int o = idx / CK;
        g_wh[idx] = __float2half(dcn_w[idx] * g_inv2[o]);
    }
}

// split p1 weights (scaled by inv1) into fp16 hi/lo
__global__ void split_w1_kernel(const float* __restrict__ p1_w)
{
    int idx = blockIdx.x * 256 + threadIdx.x;
    if (idx < C * C) {
        int o = idx >> 8;
        float v = p1_w[idx] * g_inv1[o];
        __half hi = __float2half(v);
        g_w1h[idx] = hi;
        g_w1l[idx] = __float2half(v - __half2float(hi));
    }
}

// feature -> fp16 hi/lo
__global__ void conv_f16_kernel(const float* __restrict__ feature)
{
    size_t idx = (size_t)blockIdx.x * 256 + threadIdx.x;
    if (idx < (size_t)BATCH * CHW) {
        float v = feature[idx];
        __half hi = __float2half(v);
        g_fh[idx] = hi;
        g_fl[idx] = __float2half(v - __half2float(hi));
    }
}

// repack offset weights: off_w[27][512][3][3] -> g_owh [tap(9)][32][512] fp16
__global__ void prep_offw_kernel(const float* __restrict__ off_w)
{
    int idx = blockIdx.x * 256 + threadIdx.x;
    if (idx < 9 * 32 * 512) {
        int t = idx >> 14;
        int r = (idx >> 9) & 31;
        int c = idx & 511;
        float v = 0.0f;
        if (r < 27) {
            int kh = t / 3, kw = t % 3;
            v = off_w[((size_t)(r * 512 + c) * 3 + kh) * 3 + kw];
        }
        g_owh[idx] = __float2half(v);
    }
}

// zero the padding ring of g_xh
__global__ void zero_pad_kernel()
{
    int idx = blockIdx.x * 256 + threadIdx.x;
    if (idx < BATCH * 260 * 512) {
        int c = idx & 511;
        int rest = idx >> 9;
        int pos = rest % 260;
        int b = rest / 260;
        int yp, xp;
        if (pos < 66)       { yp = 0;  xp = pos; }
        else if (pos < 132) { yp = 65; xp = pos - 66; }
        else {
            int i = pos - 132;
            yp = 1 + (i >> 1);
            xp = (i & 1) * 65;
        }
        size_t a = ((size_t)b * PP + yp * PDIM + xp) * 512 + c;
        g_xh[a] = __float2half(0.0f);
    }
}

// pack concat(flip(feature), proj) transposed -> X^T[b][pad pos][512] fp16
__global__ void __launch_bounds__(256)
pack_kernel(const float* __restrict__ feature)
{
    __shared__ float tile[32][33];
    const int tx = threadIdx.x, ty = threadIdx.y;
    const int b = blockIdx.z >> 6;
    const int y = blockIdx.z & 63;
    const int x0 = blockIdx.x * 32;
    const int c0 = blockIdx.y * 32;

#pragma unroll
    for (int j = 0; j < 4; j++) {
        int c = c0 + ty + j * 8;
        int x = x0 + tx;
        float v;
        if (c < 256) v = feature[((size_t)(b * 256 + c) * 64 + y) * 64 + (63 - x)];
        else         v = g_proj[((size_t)(b * 256 + (c - 256)) * 64 + y) * 64 + x];
        tile[ty + j * 8][tx] = v;
    }
    __syncthreads();
#pragma unroll
    for (int j = 0; j < 4; j++) {
        int xl = ty + j * 8;
        float v = tile[tx][xl];
        size_t a = ((size_t)b * PP + (y + 1) * PDIM + (x0 + xl + 1)) * 512 + c0 + tx;
        g_xh[a] = __float2half(v);
    }
}

// ---------------- proj GEMM: mma.sync fp16 3-term --------------------------
#define PJ_NCH 8
#define PJ_ASTR 40
#define PJ_BSTR 136
#define PJ_A_BYTES (128 * PJ_ASTR * 2)               // 10240
#define PJ_B_BYTES (32 * PJ_BSTR * 2)                // 8704
#define PJ_STAGE (2 * PJ_A_BYTES + 2 * PJ_B_BYTES)   // 37888
#define PJ_SMEM (2 * PJ_STAGE)                       // 75776

__global__ void __launch_bounds__(256, 1)
proj_tc_kernel()
{
    extern __shared__ char smem[];
    const uint32_t sbase = smem_to_u32(smem);
    const int tid = threadIdx.x;
    const int lane = tid & 31;
    const int wid = tid >> 5;

    const int n0 = blockIdx.x * 128;
    const int m0 = blockIdx.y * 128;
    const int bb = n0 >> 12;
    const int hw0 = n0 & 4095;
    const int wm = (wid >> 2) * 64;
    const int wn = (wid & 3) * 32;

    const __half* wh = g_w1h + (size_t)m0 * C;
    const __half* wl = g_w1l + (size_t)m0 * C;
    const __half* fh = g_fh + (size_t)bb * CHW + hw0;
    const __half* fl = g_fl + (size_t)bb * CHW + hw0;

    float acc[4][4][4];
#pragma unroll
    for (int i = 0; i < 4; i++)
#pragma unroll
        for (int j = 0; j < 4; j++)
#pragma unroll
            for (int t = 0; t < 4; t++) acc[i][j][t] = 0.0f;

    auto load_chunk = [&](int st, int kt) {
        const uint32_t s = sbase + st * PJ_STAGE;
        const int k0 = kt * 32;
#pragma unroll
        for (int i = 0; i < 2; i++) {
            int idx = i * 256 + tid;
            int r = idx >> 2, kseg = idx & 3;
            size_t go = (size_t)r * C + k0 + kseg * 8;
            uint32_t so = (uint32_t)(r * PJ_ASTR + kseg * 8) * 2;
            cp16(s + so, wh + go);
            cp16(s + PJ_A_BYTES + so, wl + go);
        }
#pragma unroll
        for (int i = 0; i < 2; i++) {
            int idx = i * 256 + tid;
            int kr = idx >> 4, nseg = idx & 15;
            size_t go = (size_t)(k0 + kr) * HW + nseg * 8;
            uint32_t so = (uint32_t)(kr * PJ_BSTR + nseg * 8) * 2;
            cp16(s + 2 * PJ_A_BYTES + so, fh + go);
            cp16(s + 2 * PJ_A_BYTES + PJ_B_BYTES + so, fl + go);
        }
        CP_COMMIT();
    };

    load_chunk(0, 0);

    for (int kt = 0; kt < PJ_NCH; kt++) {
        const int st = kt & 1;
        if (kt + 1 < PJ_NCH) { load_chunk(st ^ 1, kt + 1); CP_WAIT(1); }
        else                 { CP_WAIT(0); }
        __syncthreads();

        const uint32_t sAh = sbase + st * PJ_STAGE;
        const uint32_t sAl = sAh + PJ_A_BYTES;
        const uint32_t sBh = sAh + 2 * PJ_A_BYTES;
        const uint32_t sBl = sBh + PJ_B_BYTES;

#pragma unroll
        for (int ks = 0; ks < 2; ks++) {
            uint32_t ah[4][4], al[4][4], bh[4][2], bl[4][2];

            const int arow = wm + (lane & 15);
            const int acol = ks * 16 + ((lane >> 4) << 3);
#pragma unroll
            for (int tm = 0; tm < 4; tm++) {
                uint32_t ao = (uint32_t)((arow + tm * 16) * PJ_ASTR + acol) * 2;
                ldsm4(ah[tm], sAh + ao);
                ldsm4(al[tm], sAl + ao);
            }
            const int bkrow = ks * 16 + (lane & 15);
#pragma unroll
            for (int ng = 0; ng < 2; ng++) {
                const int bcol = wn + ng * 16 + ((lane >> 4) << 3);
                uint32_t bo = (uint32_t)(bkrow * PJ_BSTR + bcol) * 2;
                uint32_t t[4];
                ldsm4t(t, sBh + bo);
                bh[2*ng][0] = t[0]; bh[2*ng][1] = t[1];
                bh[2*ng+1][0] = t[2]; bh[2*ng+1][1] = t[3];
                ldsm4t(t, sBl + bo);
                bl[2*ng][0] = t[0]; bl[2*ng][1] = t[1];
                bl[2*ng+1][0] = t[2]; bl[2*ng+1][1] = t[3];
            }
#pragma unroll
            for (int tm = 0; tm < 4; tm++)
#pragma unroll
                for (int tn = 0; tn < 4; tn++) {
                    mma_fp(acc[tm][tn], ah[tm], bh[tn]);
                    mma_fp(acc[tm][tn], ah[tm], bl[tn]);
                    mma_fp(acc[tm][tn], al[tm], bh[tn]);
                }
        }
        __syncthreads();
    }

    const int rowl = lane >> 2;
    const int colp = (lane & 3) * 2;
#pragma unroll
    for (int tm = 0; tm < 4; tm++) {
#pragma unroll
        for (int half = 0; half < 2; half++) {
            const int m = m0 + wm + tm * 16 + rowl + half * 8;
            const float add = g_add1[m];
            float* ob = g_proj + ((size_t)bb * C + m) * HW + hw0 + wn + colp;
#pragma unroll
            for (int tn = 0; tn < 4; tn++) {
                float2 r;
                r.x = acc[tm][tn][half * 2 + 0] + add;
                r.y = acc[tm][tn][half * 2 + 1] + add;
                *(float2*)(ob + tn * 8) = r;
            }
        }
    }
}

// ---------------- offset conv as tensor-core GEMM (fp16 single, 3-stage) ---
#define OC_ROWS 396
#define OC_BSTR 40
#define OC_ASTR 40
#define OC_B_BYTES (OC_ROWS * OC_BSTR * 2)         // 31680
#define OC_A_BYTES (9 * 32 * OC_ASTR * 2)          // 23040
#define OC_STAGE (OC_B_BYTES + OC_A_BYTES)         // 54720
#define OC_SMEM (3 * OC_STAGE)                     // 164160

__global__ void __launch_bounds__(256, 1)
off_gemm_kernel(const float* __restrict__ off_b)
{
    extern __shared__ char smem[];
    const uint32_t sbase = smem_to_u32(smem);
    const int tid = threadIdx.x;
    const int lane = tid & 31;
    const int wid = tid >> 5;

    const int n0 = blockIdx.x * 256;
    const int bb = n0 >> 12;
    const int hw0 = n0 & 4095;
    const int h0 = hw0 >> 6;

    const int wm = (wid >> 2) * 16;
    const int wn = (wid & 3) * 64;

    const size_t pbase = (size_t)bb * PP + h0 * PDIM;

    uint32_t rowb[8];
#pragma unroll
    for (int nt = 0; nt < 8; nt++) {
        int nl = wn + nt * 8 + (lane >> 2);
        int row = ((nl >> 6) + 1) * PDIM + (nl & 63) + 1;
        rowb[nt] = (uint32_t)(row * OC_BSTR + (lane & 3) * 2) * 2;
    }
    const int am = wm + (lane & 15);
    const int acol2 = (lane >> 4) << 3;

    float acc[8][4];
#pragma unroll
    for (int i = 0; i < 8; i++)
#pragma unroll
        for (int j = 0; j < 4; j++) acc[i][j] = 0.0f;

    auto load_chunk = [&](int st, int kc) {
        const uint32_t s = sbase + st * OC_STAGE;
        const int k0 = kc * 32;
#pragma unroll
        for (int i = 0; i < 7; i++) {
            int idx = i * 256 + tid;
            if (idx < 1584) {
                int r = idx >> 2, c4 = idx & 3;
                size_t go = (pbase + r) * 512 + k0 + c4 * 8;
                uint32_t so = (uint32_t)(r * OC_BSTR + c4 * 8) * 2;
                cp16(s + so, g_xh + go);
            }
        }
#pragma unroll
        for (int i = 0; i < 5; i++) {
            int idx = i * 256 + tid;
            if (idx < 1152) {
                int r = idx >> 2, c4 = idx & 3;
                size_t go = (size_t)r * 512 + k0 + c4 * 8;
                uint32_t so = (uint32_t)(r * OC_ASTR + c4 * 8) * 2;
                cp16(s + OC_B_BYTES + so, g_owh + go);
            }
        }
        CP_COMMIT();
    };

    const int stapB[9] = {(-PDIM-1)*OC_BSTR*2, (-PDIM)*OC_BSTR*2, (-PDIM+1)*OC_BSTR*2,
                          (-1)*OC_BSTR*2, 0, (1)*OC_BSTR*2,
                          (PDIM-1)*OC_BSTR*2, (PDIM)*OC_BSTR*2, (PDIM+1)*OC_BSTR*2};

    load_chunk(0, 0);
    load_chunk(1, 1);

    int st = 0;
    for (int kc = 0; kc < 16; kc++) {
        if (kc + 2 < 16) load_chunk((st + 2) % 3, kc + 2);
        else             CP_COMMIT();
        CP_WAIT(2);
        __syncthreads();

        const uint32_t sB  = sbase + st * OC_STAGE;
        const uint32_t sAh = sB + OC_B_BYTES;

#pragma unroll
        for (int tap = 0; tap < 9; tap++) {
            const int sb_t = stapB[tap];
#pragma unroll
            for (int ks = 0; ks < 2; ks++) {
                uint32_t ah[4];
                uint32_t ao = (uint32_t)((tap * 32 + am) * OC_ASTR + ks * 16 + acol2) * 2;
                ldsm4(ah, sAh + ao);
#pragma unroll
                for (int nt = 0; nt < 8; nt++) {
                    uint32_t base = sB + rowb[nt] + sb_t + ks * 32;
                    uint32_t b[2];
                    b[0] = lds32(base);
                    b[1] = lds32(base + 16);
                    mma_fp(acc[nt], ah, b);
                }
            }
        }
        __syncthreads();
        st = (st + 1) % 3;
    }

    const int mr = wm + (lane >> 2);
    const int cb = hw0 + wn + (lane & 3) * 2;
#pragma unroll
    for (int half = 0; half < 2; half++) {
        int m = mr + half * 8;
        if (m < 27) {
            float bias = off_b[m];
            float* ob = g_off + ((size_t)(bb * 27 + m)) * HW + cb;
#pragma unroll
            for (int nt = 0; nt < 8; nt++) {
                float2 r;
                r.x = acc[nt][half * 2 + 0] + bias;
                r.y = acc[nt][half * 2 + 1] + bias;
                *(float2*)(ob + nt * 8) = r;
            }
        }
    }
}

// ---------------- deformable sampling -> fp16 im2col (mask folded) ---------
__global__ void __launch_bounds__(256)
sample_kernel(const float* __restrict__ feature)
{
    const int tid = threadIdx.x;
    const int w  = tid & 63;
    const int cg = tid >> 6;
    const int h  = blockIdx.x;
    const int k  = blockIdx.y;
    const int b  = blockIdx.z;

    const int hw = h * W + w;
    const int p  = b * HW + hw;
    const size_t obase = (size_t)(b * 27) * HW + hw;

    const float dy = g_off[obase + (size_t)k * HW];
    const float dx = g_off[obase + (size_t)(9 + k) * HW];
    const float mr = g_off[obase + (size_t)(18 + k) * HW];
    const float m  = 1.0f / (1.0f + expf(-mr));

    const int ky = k / 3 - 1, kx = k % 3 - 1;
    const float py = (float)(h + ky) + dy;
    const float px = (float)(w + kx) + dx;

    const float y0f = floorf(py), x0f = floorf(px);
    const float wy = py - y0f, wx = px - x0f;
    const int y0 = (int)y0f, x0 = (int)x0f;
    const int y1 = y0 + 1,   x1 = x0 + 1;

    const bool vy0 = (y0 >= 0) && (y0 < H);
    const bool vy1 = (y1 >= 0) && (y1 < H);
    const bool vx0 = (x0 >= 0) && (x0 < W);
    const bool vx1 = (x1 >= 0) && (x1 < W);

    float w00 = (1.0f - wy) * (1.0f - wx) * ((vy0 && vx0) ? 1.0f : 0.0f);
    float w01 = (1.0f - wy) * wx          * ((vy0 && vx1) ? 1.0f : 0.0f);
    float w10 = wy * (1.0f - wx)          * ((vy1 && vx0) ? 1.0f : 0.0f);
    float w11 = wy * wx                   * ((vy1 && vx1) ? 1.0f : 0.0f);
    w00 *= m; w01 *= m; w10 *= m; w11 *= m;

    const int yc0 = min(max(y0, 0), H - 1);
    const int yc1 = min(max(y1, 0), H - 1);
    const int xc0 = min(max(x0, 0), W - 1);
    const int xc1 = min(max(x1, 0), W - 1);

    const int a00 = yc0 * W + (63 - xc0);
    const int a01 = yc0 * W + (63 - xc1);
    const int a10 = yc1 * W + (63 - xc0);
    const int a11 = yc1 * W + (63 - xc1);

    const float* fb = feature + (size_t)b * CHW + (size_t)(cg * 64) * HW;
    size_t cidx = ((size_t)(cg * 64) * KK + k) * NPIX + p;

#pragma unroll 4
    for (int c = 0; c < 64; c++) {
        float v = w00 * fb[a00] + w01 * fb[a01] + w10 * fb[a10] + w11 * fb[a11];
        g_colh[cidx] = __float2half(v);
        fb += HW;
        cidx += (size_t)KK * NPIX;
    }
}

// ---------------- DCN GEMM: mma.sync fp16 single-term, 3-stage -------------
#define DCN_NCH 72
#define A_STRIDE 40
#define B_STRIDE 136
#define A_BYTES (128 * A_STRIDE * 2)                 // 10240
#define B_BYTES (32 * B_STRIDE * 2)                  // 8704
#define STAGE_BYTES (A_BYTES + B_BYTES)              // 18944
#define DCN_SMEM (3 * STAGE_BYTES)                   // 56832

__global__ void __launch_bounds__(256, 1)
dcn_gemm_kernel(float* __restrict__ out)
{
    extern __shared__ char smem[];
    const uint32_t sbase = smem_to_u32(smem);
    const int tid = threadIdx.x;
    const int lane = tid & 31;
    const int wid = tid >> 5;

    const int n0 = blockIdx.x * 128;
    const int m0 = blockIdx.y * 128;
    const int bb = n0 >> 12;
    const int hw0 = n0 & 4095;
    const int wm = (wid >> 2) * 64;
    const int wn = (wid & 3) * 32;

    const __half* wh = g_wh + (size_t)m0 * CK;

    float acc[4][4][4];
#pragma unroll
    for (int i = 0; i < 4; i++)
#pragma unroll
        for (int j = 0; j < 4; j++)
#pragma unroll
            for (int t = 0; t < 4; t++) acc[i][j][t] = 0.0f;

    auto load_chunk = [&](int st, int kt) {
        const uint32_t s = sbase + st * STAGE_BYTES;
        const int k0 = kt * 32;
#pragma unroll
        for (int i = 0; i < 2; i++) {
            int idx = i * 256 + tid;
            int r = idx >> 2, kseg = idx & 3;
            size_t go = (size_t)r * CK + k0 + kseg * 8;
            uint32_t so = (uint32_t)(r * A_STRIDE + kseg * 8) * 2;
            cp16(s + so, wh + go);
        }
#pragma unroll
        for (int i = 0; i < 2; i++) {
            int idx = i * 256 + tid;
            int kr = idx >> 4, nseg = idx & 15;
            size_t go = (size_t)(k0 + kr) * NPIX + n0 + nseg * 8;
            uint32_t so = (uint32_t)(kr * B_STRIDE + nseg * 8) * 2;
            cp16(s + A_BYTES + so, g_colh + go);
        }
        CP_COMMIT();
    };

    load_chunk(0, 0);
    load_chunk(1, 1);

    int st = 0;
    for (int kt = 0; kt < DCN_NCH; kt++) {
        if (kt + 2 < DCN_NCH) load_chunk((st + 2) % 3, kt + 2);
        else                  CP_COMMIT();
        CP_WAIT(2);
        __syncthreads();

        const uint32_t sA = sbase + st * STAGE_BYTES;
        const uint32_t sB = sA + A_BYTES;

#pragma unroll
        for (int ks = 0; ks < 2; ks++) {
            uint32_t ah[4][4], bf[4][2];

            const int arow = wm + (lane & 15);
            const int acol = ks * 16 + ((lane >> 4) << 3);
#pragma unroll
            for (int tm = 0; tm < 4; tm++) {
                uint32_t ao = (uint32_t)((arow + tm * 16) * A_STRIDE + acol) * 2;
                ldsm4(ah[tm], sA + ao);
            }
            const int bkrow = ks * 16 + (lane & 15);
#pragma unroll
            for (int ng = 0; ng < 2; ng++) {
                const int bcol = wn + ng * 16 + ((lane >> 4) << 3);
                uint32_t bo = (uint32_t)(bkrow * B_STRIDE + bcol) * 2;
                uint32_t t[4];
                ldsm4t(t, sB + bo);
                bf[2*ng][0] = t[0]; bf[2*ng][1] = t[1];
                bf[2*ng+1][0] = t[2]; bf[2*ng+1][1] = t[3];
            }
#pragma unroll
            for (int tm = 0; tm < 4; tm++)
#pragma unroll
                for (int tn = 0; tn < 4; tn++)
                    mma_fp(acc[tm][tn], ah[tm], bf[tn]);
        }
        __syncthreads();
        st = (st + 1) % 3;
    }

    const int rowl = lane >> 2;
    const int colp = (lane & 3) * 2;
#pragma unroll
    for (int tm = 0; tm < 4; tm++) {
#pragma unroll
        for (int half = 0; half < 2; half++) {
            const int m = m0 + wm + tm * 16 + rowl + half * 8;
            const float add = g_add2[m];
            const float* pr = g_proj + ((size_t)bb * C + m) * HW + hw0 + wn + colp;
            float*       ob = out    + ((size_t)bb * C + m) * HW + hw0 + wn + colp;
#pragma unroll
            for (int tn = 0; tn < 4; tn++) {
                float2 p = *(const float2*)(pr + tn * 8);
                float2 r;
                r.x = fmaxf(acc[tm][tn][half * 2 + 0] + add + p.x, 0.0f);
                r.y = fmaxf(acc[tm][tn][half * 2 + 1] + add + p.y, 0.0f);
                *(float2*)(ob + tn * 8) = r;
            }
        }
    }
}

// ---------------- launch ----------------------------------------------------
extern "C" void kernel_launch(void* const* d_in, const int* in_sizes, int n_in,
                              void* d_out, int out_size)
{
    const float* feature = (const float*)d_in[0];
    const float* p1_w    = (const float*)d_in[1];
    const float* p1_b    = (const float*)d_in[2];
    const float* bn1_g   = (const float*)d_in[3];
    const float* bn1_b   = (const float*)d_in[4];
    const float* bn1_m   = (const float*)d_in[5];
    const float* bn1_v   = (const float*)d_in[6];
    const float* off_w   = (const float*)d_in[7];
    const float* off_b   = (const float*)d_in[8];
    const float* dcn_w   = (const float*)d_in[9];
    const float* dcn_b   = (const float*)d_in[10];
    const float* bn2_g   = (const float*)d_in[11];
    const float* bn2_b   = (const float*)d_in[12];
    const float* bn2_m   = (const float*)d_in[13];
    const float* bn2_v   = (const float*)d_in[14];

    cudaFuncSetAttribute(dcn_gemm_kernel,
                         cudaFuncAttributeMaxDynamicSharedMemorySize, DCN_SMEM);
    cudaFuncSetAttribute(off_gemm_kernel,
                         cudaFuncAttributeMaxDynamicSharedMemorySize, OC_SMEM);
    cudaFuncSetAttribute(proj_tc_kernel,
                         cudaFuncAttributeMaxDynamicSharedMemorySize, PJ_SMEM);

    prep_kernel<<<1, 256>>>(p1_b, bn1_g, bn1_b, bn1_m, bn1_v,
                            dcn_b, bn2_g, bn2_b, bn2_m, bn2_v);
    split_w_kernel<<<(C * CK + 255) / 256, 256>>>(dcn_w);
    split_w1_kernel<<<(C * C + 255) / 256, 256>>>(p1_w);
    conv_f16_kernel<<<(int)(((size_t)BATCH * CHW + 255) / 256), 256>>>(feature);
    prep_offw_kernel<<<(9 * 32 * 512 + 255) / 256, 256>>>(off_w);
    zero_pad_kernel<<<(BATCH * 260 * 512 + 255) / 256, 256>>>();

    proj_tc_kernel<<<dim3(NPIX / 128, 2), 256, PJ_SMEM>>>();

    pack_kernel<<<dim3(2, 16, 512), dim3(32, 8)>>>(feature);

    off_gemm_kernel<<<NPIX / 256, 256, OC_SMEM>>>(off_b);

    sample_kernel<<<dim3(H, KK, BATCH), 256>>>(feature);

    dcn_gemm_kernel<<<dim3(NPIX / 128, C / 128), 256, DCN_SMEM>>>((float*)d_out);
}